// round 12
// baseline (speedup 1.0000x reference)
#include <cuda_runtime.h>
#include <cuda_fp16.h>
#include <cstdint>

// ===========================================================================
// Problem constants (fixed: B=4, C=32, H=W=128, scale=2)
// ===========================================================================
#define Bn    4
#define Cn    32
#define Hn    128
#define Wn    128
#define QPB   65536
#define NQ    (Bn * QPB)
#define MT    64                   // queries per CTA
#define NCTA  (NQ / MT)            // 4096
#define NRB   4                    // row-blocks (16 rows) per CTA

// ===========================================================================
// Global scratch
// ===========================================================================
__device__ float g_xt[Bn * Hn * Wn * Cn];   // channels-last x

// Weight images: B-fragment-packed fp16.
#define WOFF_L1  0u          // KC=3,  NPT=16 -> 24576
#define WOFF_L2  24576u      // KC=16, NPT=16 -> 131072
#define WOFF_L3  155648u     // KC=16, NPT=2  -> 16384
#define WOFF_R0  172032u     // KC=2,  NPT=16 -> 16384
#define WOFF_R1  188416u     // KC=16, NPT=2  -> 16384
#define WOFF_O0  204800u     // KC=2,  NPT=16 -> 16384
#define WOFF_O1  221184u     // KC=16, NPT=1  -> 8192
#define WIMG_TOTAL 229376u
__device__ __align__(16) unsigned char g_wimg[WIMG_TOTAL];

// ===========================================================================
// Setup kernel: y==0 -> transpose x; y>=1 -> weight prep for layer y-1.
// ===========================================================================
__global__ void setup_kernel(const float* __restrict__ x,
                             const float* __restrict__ w0, const float* __restrict__ w1,
                             const float* __restrict__ w2, const float* __restrict__ rw0,
                             const float* __restrict__ rw1, const float* __restrict__ ow0,
                             const float* __restrict__ ow1) {
    const int tid = threadIdx.x;
    if (blockIdx.y == 0) {
        __shared__ float s[Cn][Wn + 1];
        const int by = blockIdx.x;      // 0..511
#pragma unroll
        for (int it = 0; it < 16; ++it) {
            int idx = tid + it * 256;
            int c = idx >> 7, xc = idx & 127;
            int b = by >> 7, y = by & 127;
            s[c][xc] = x[((b * Cn + c) * Hn + y) * Wn + xc];
        }
        __syncthreads();
#pragma unroll
        for (int it = 0; it < 16; ++it) {
            int idx = tid + it * 256;
            int xc = idx >> 5, c = idx & 31;
            g_xt[(by * Wn + xc) * Cn + c] = s[c][xc];
        }
        return;
    }
    const float* W;
    int Kdim, Ndim, Kt, Nt;
    uint32_t dstOff;
    switch (blockIdx.y - 1) {
        case 0: W = w0;  Kdim = 36;  Ndim = 256; Kt = 48;  Nt = 256; dstOff = WOFF_L1; break;
        case 1: W = w1;  Kdim = 256; Ndim = 256; Kt = 256; Nt = 256; dstOff = WOFF_L2; break;
        case 2: W = w2;  Kdim = 256; Ndim = 32;  Kt = 256; Nt = 32;  dstOff = WOFF_L3; break;
        case 3: W = rw0; Kdim = 32;  Ndim = 256; Kt = 32;  Nt = 256; dstOff = WOFF_R0; break;
        case 4: W = rw1; Kdim = 256; Ndim = 32;  Kt = 256; Nt = 32;  dstOff = WOFF_R1; break;
        case 5: W = ow0; Kdim = 32;  Ndim = 256; Kt = 32;  Nt = 256; dstOff = WOFF_O0; break;
        default: W = ow1; Kdim = 256; Ndim = 2;  Kt = 256; Nt = 16;  dstOff = WOFF_O1; break;
    }
    int idx = blockIdx.x * 256 + tid;
    if (idx >= Kt * Nt) return;
    int k = idx / Nt;
    int n = idx % Nt;
    float w = (k < Kdim && n < Ndim) ? W[k * Ndim + n] : 0.0f;
    __half hb = __float2half_rn(w);
    int kc = k >> 4, ki = k & 15;
    int nc = n >> 3, ni = n & 7;
    int npair = nc >> 1;
    int lane = ni * 4 + ((ki & 7) >> 1);
    int word = (ki >> 3) + (nc & 1) * 2;
    int half = ki & 1;
    uint32_t off = (uint32_t)(((kc * (Nt >> 4) + npair) * 32 + lane) * 16 +
                              word * 4 + half * 2);
    *reinterpret_cast<unsigned short*>(g_wimg + dstOff + off) = __half_as_ushort(hb);
}

// ===========================================================================
// Bicubic helpers (torch aten, A=-0.75)
// ===========================================================================
__device__ __forceinline__ void prep_axis(float g, int& i0, float w[4]) {
    float p = ((g + 1.0f) * 128.0f - 1.0f) * 0.5f;
    float fp = floorf(p);
    i0 = (int)fp;
    float t = p - fp;
    const float A = -0.75f;
    float xx = t + 1.0f;
    w[0] = ((A * xx - 5.0f * A) * xx + 8.0f * A) * xx - 4.0f * A;
    w[1] = ((A + 2.0f) * t - (A + 3.0f)) * t * t + 1.0f;
    float s = 1.0f - t;
    w[2] = ((A + 2.0f) * s - (A + 3.0f)) * s * s + 1.0f;
    w[3] = 1.0f - w[0] - w[1] - w[2];
}

__device__ __forceinline__ float sample_c(const float* __restrict__ xb, int lane,
                                          int ix0, int iy0,
                                          const float* wx, const float* wy) {
    float acc = 0.0f;
#pragma unroll
    for (int i = 0; i < 4; ++i) {
        int yi = iy0 - 1 + i;
        if ((unsigned)yi < 128u) {
            const float* rp = xb + yi * (Wn * Cn) + lane;
            float r = 0.0f;
#pragma unroll
            for (int j = 0; j < 4; ++j) {
                int xj = ix0 - 1 + j;
                if ((unsigned)xj < 128u) r = fmaf(wx[j], __ldg(rp + xj * Cn), r);
            }
            acc = fmaf(wy[i], r, acc);
        }
    }
    return acc;
}

// packed fp16x2 (v1 in high half, v0 in low half)
__device__ __forceinline__ uint32_t pack_h2(float v0, float v1) {
    __half2 h = __floats2half2_rn(v0, v1);
    return *reinterpret_cast<uint32_t*>(&h);
}

// ===========================================================================
// mma.sync m16n8k16 fp16
// ===========================================================================
__device__ __forceinline__ void mma_f16(float* c, const uint4& a,
                                        uint32_t b0, uint32_t b1) {
    asm("mma.sync.aligned.m16n8k16.row.col.f32.f16.f16.f32 "
        "{%0,%1,%2,%3},{%4,%5,%6,%7},{%8,%9},{%0,%1,%2,%3};"
        : "+f"(c[0]), "+f"(c[1]), "+f"(c[2]), "+f"(c[3])
        : "r"(a.x), "r"(a.y), "r"(a.z), "r"(a.w), "r"(b0), "r"(b1));
}

// Wide K-loop over ALL 4 row blocks, single-term: C += A*B.
// Each warp owns a UNIQUE N-slice -> weight LDG not duplicated across warps.
template <int KC, int NC, int NPT>
__device__ __forceinline__ void mma_layer(const uint4* __restrict__ aHi,
                                          const uint4* __restrict__ bHi,
                                          int nc0, float C[NRB][NC][4]) {
    const int lane = threadIdx.x & 31;
#pragma unroll
    for (int r = 0; r < NRB; ++r)
#pragma unroll
        for (int j = 0; j < NC; ++j)
#pragma unroll
            for (int t = 0; t < 4; ++t) C[r][j][t] = 0.0f;
    const int npair0 = nc0 >> 1;
#pragma unroll 1
    for (int kc = 0; kc < KC; ++kc) {
        uint4 a0 = aHi[(kc * NRB + 0) * 32 + lane];
        uint4 a1 = aHi[(kc * NRB + 1) * 32 + lane];
        uint4 a2 = aHi[(kc * NRB + 2) * 32 + lane];
        uint4 a3 = aHi[(kc * NRB + 3) * 32 + lane];
#pragma unroll
        for (int p = 0; p < NC / 2; ++p) {
            uint4 bh = __ldg(bHi + (kc * NPT + npair0 + p) * 32 + lane);
            mma_f16(C[0][2 * p], a0, bh.x, bh.y);
            mma_f16(C[1][2 * p], a1, bh.x, bh.y);
            mma_f16(C[2][2 * p], a2, bh.x, bh.y);
            mma_f16(C[3][2 * p], a3, bh.x, bh.y);
            mma_f16(C[0][2 * p + 1], a0, bh.z, bh.w);
            mma_f16(C[1][2 * p + 1], a1, bh.z, bh.w);
            mma_f16(C[2][2 * p + 1], a2, bh.z, bh.w);
            mma_f16(C[3][2 * p + 1], a3, bh.z, bh.w);
        }
    }
}

// Partial K-slice for narrow (N<=32) layers: one npair, kc in [kc0, kc0+kcn).
__device__ __forceinline__ void mma_part(const uint4* __restrict__ aHi,
                                         const uint4* __restrict__ bHi,
                                         int npair0, int kc0, int kcn, int NPT,
                                         float C[NRB][2][4]) {
    const int lane = threadIdx.x & 31;
#pragma unroll
    for (int r = 0; r < NRB; ++r)
#pragma unroll
        for (int j = 0; j < 2; ++j)
#pragma unroll
            for (int t = 0; t < 4; ++t) C[r][j][t] = 0.0f;
#pragma unroll 1
    for (int kc = kc0; kc < kc0 + kcn; ++kc) {
        uint4 bh = __ldg(bHi + (kc * NPT + npair0) * 32 + lane);
#pragma unroll
        for (int r = 0; r < NRB; ++r) {
            uint4 a = aHi[(kc * NRB + r) * 32 + lane];
            mma_f16(C[r][0], a, bh.x, bh.y);
            mma_f16(C[r][1], a, bh.z, bh.w);
        }
    }
}

// Store a warp's narrow-layer partials to scratch (conflict-free float4 layout).
// scr4 layout: [i (rb*2+j) 0..7][slice 0..7][lane]
__device__ __forceinline__ void store_part(float4* scr4, int slice,
                                           float C[NRB][2][4]) {
    const int lane = threadIdx.x & 31;
#pragma unroll
    for (int r = 0; r < NRB; ++r)
#pragma unroll
        for (int j = 0; j < 2; ++j) {
            int i = r * 2 + j;
            scr4[(i * 8 + slice) * 32 + lane] =
                make_float4(C[r][j][0], C[r][j][1], C[r][j][2], C[r][j][3]);
        }
}

// Reduce 4 k-slices (slices nh, nh+2, nh+4, nh+6) for n-half nh.
__device__ __forceinline__ void reduce4(const float4* scr4, int nh,
                                        float C[NRB][2][4]) {
    const int lane = threadIdx.x & 31;
#pragma unroll
    for (int i = 0; i < 8; ++i) {
        float4 a = scr4[(i * 8 + nh) * 32 + lane];
        float4 b = scr4[(i * 8 + 2 + nh) * 32 + lane];
        float4 c = scr4[(i * 8 + 4 + nh) * 32 + lane];
        float4 d = scr4[(i * 8 + 6 + nh) * 32 + lane];
        C[i >> 1][i & 1][0] = (a.x + b.x) + (c.x + d.x);
        C[i >> 1][i & 1][1] = (a.y + b.y) + (c.y + d.y);
        C[i >> 1][i & 1][2] = (a.z + b.z) + (c.z + d.z);
        C[i >> 1][i & 1][3] = (a.w + b.w) + (c.w + d.w);
    }
}

// Epilogue: bias(+ReLU), pack fp16 A fragments for the next layer.
template <int NC, bool RELU>
__device__ __forceinline__ void epi_region(float C[NRB][NC][4],
                                           const float* __restrict__ biasp,
                                           int nc0, uint32_t* dHi) {
    const int lane = threadIdx.x & 31;
    const int q = (lane & 3) * 2;
#pragma unroll
    for (int j = 0; j < NC; ++j) {
        int nc = nc0 + j;
        int kc = nc >> 1, odd = nc & 1;
        float b0 = __ldg(biasp + nc * 8 + q);
        float b1 = __ldg(biasp + nc * 8 + q + 1);
#pragma unroll
        for (int r = 0; r < NRB; ++r) {
            float v0 = C[r][j][0] + b0, v1 = C[r][j][1] + b1;
            float v2 = C[r][j][2] + b0, v3 = C[r][j][3] + b1;
            if (RELU) {
                v0 = fmaxf(v0, 0.f); v1 = fmaxf(v1, 0.f);
                v2 = fmaxf(v2, 0.f); v3 = fmaxf(v3, 0.f);
            }
            int base = ((kc * NRB + r) * 32 + lane) * 4 + odd * 2;
            dHi[base] = pack_h2(v0, v1);
            dHi[base + 1] = pack_h2(v2, v3);
        }
    }
}

// ===========================================================================
// SMEM layout (bytes) — total 64384; 2 CTAs/SM (RF-limited)
// ===========================================================================
#define SM_INPF  0          // fp32 [64][49] = 12544 (reused as routs [64][33])
#define SM_SHI   12544      // inp frags: 3*4*512 = 6144
#define SM_PHI   18688      // pred frags: 2*4*512 = 4096
#define SM_AHI   22784      // act frags: 16*4*512 = 32768 (doubles as scratch)
#define SM_OFFS  55552      // fp32 [64][2] = 512
#define SM_OUT   56064      // fp32 [32][65] = 8320
#define SMEM_BYTES 64384

// ===========================================================================
// Fused kernel: 64 queries per CTA, 8 warps, 2 CTAs/SM.
// Wide layers: warp = unique 32 N-cols, ALL 4 row-blocks.
// Narrow layers: k-split over all warps.
// ===========================================================================
__global__ __launch_bounds__(256, 2) void fused_kernel(
    const float* __restrict__ b0p, const float* __restrict__ b1p,
    const float* __restrict__ b2p, const float* __restrict__ rb0p,
    const float* __restrict__ rb1p, const float* __restrict__ ob0p,
    const float* __restrict__ ob1p, float* __restrict__ out) {
    extern __shared__ __align__(16) unsigned char smraw[];
    float* inpF = reinterpret_cast<float*>(smraw + SM_INPF);
    uint4* SHi = reinterpret_cast<uint4*>(smraw + SM_SHI);
    uint4* PHi = reinterpret_cast<uint4*>(smraw + SM_PHI);
    uint4* AHi = reinterpret_cast<uint4*>(smraw + SM_AHI);
    uint32_t* PHiW = reinterpret_cast<uint32_t*>(PHi);
    uint32_t* AHiW = reinterpret_cast<uint32_t*>(AHi);
    float4* scr4 = reinterpret_cast<float4*>(smraw + SM_AHI);  // narrow-layer scratch
    float* offs  = reinterpret_cast<float*>(smraw + SM_OFFS);
    float* outst = reinterpret_cast<float*>(smraw + SM_OUT);
    float* routs = inpF;   // reuse after L1 staging

    const int tid = threadIdx.x;
    const int lane = tid & 31;
    const int wid = tid >> 5;

    const int q0 = blockIdx.x * MT;
    const int b = q0 >> 16;
    const int qbase = q0 & (QPB - 1);
    const float* xb = g_xt + b * (Hn * Wn * Cn);

    const uint4* WL1 = (const uint4*)(g_wimg + WOFF_L1);
    const uint4* WL2 = (const uint4*)(g_wimg + WOFF_L2);
    const uint4* WL3 = (const uint4*)(g_wimg + WOFF_L3);
    const uint4* WR0 = (const uint4*)(g_wimg + WOFF_R0);
    const uint4* WR1 = (const uint4*)(g_wimg + WOFF_R1);
    const uint4* WO0 = (const uint4*)(g_wimg + WOFF_O0);
    const uint4* WO1 = (const uint4*)(g_wimg + WOFF_O1);

    // ---- Stage A: sampling -> inpF [64][49] --------------------------------
#pragma unroll 1
    for (int i = 0; i < 8; ++i) {
        int m = wid * 8 + i;
        int ql = qbase + m;
        int oy = ql >> 8, ox = ql & 255;
        float gy = (2.0f * oy + 1.0f) * (1.0f / 256.0f) - 1.0f;
        float gx = (2.0f * ox + 1.0f) * (1.0f / 256.0f) - 1.0f;
        int ix0, iy0;
        float wx[4], wy[4];
        prep_axis(gx, ix0, wx);
        prep_axis(gy, iy0, wy);
        inpF[m * 49 + lane] = sample_c(xb, lane, ix0, iy0, wx, wy);
        if (lane == 0) {
            float syw = 0.f, sy = 0.f, sxw = 0.f, sx = 0.f;
#pragma unroll
            for (int ii = 0; ii < 4; ++ii) {
                int yi = iy0 - 1 + ii;
                if ((unsigned)yi < 128u) {
                    float yco = (2.0f * yi + 1.0f) * (1.0f / 128.0f) - 1.0f;
                    syw += wy[ii]; sy = fmaf(wy[ii], yco, sy);
                }
            }
#pragma unroll
            for (int jj = 0; jj < 4; ++jj) {
                int xj = ix0 - 1 + jj;
                if ((unsigned)xj < 128u) {
                    float xco = (2.0f * xj + 1.0f) * (1.0f / 128.0f) - 1.0f;
                    sxw += wx[jj]; sx = fmaf(wx[jj], xco, sx);
                }
            }
            inpF[m * 49 + 32] = (gy - sy * sxw) * 128.0f;
            inpF[m * 49 + 33] = (gx - sx * syw) * 128.0f;
            float rc = (ql < 2) ? 1.0f : 128.0f;   // faithful cell quirk
            inpF[m * 49 + 34] = rc;
            inpF[m * 49 + 35] = rc;
        }
        if (lane >= 4 && lane < 16) inpF[m * 49 + 32 + lane] = 0.0f;  // pad 36..47
    }
    __syncthreads();

    // ---- Stage S frags: inpF -> S (A-fragment fp16, K=48) -------------------
    // 12 (kc, rb) combos over 8 warps
#pragma unroll
    for (int it = 0; it < 2; ++it) {
        int idx = wid + it * 8;
        if (idx < 12) {
            int kc = idx >> 2, rbs = idx & 3;
            int r0 = rbs * 16 + (lane >> 2);
            int k0 = kc * 16 + (lane & 3) * 2;
            uint4 hi;
            hi.x = pack_h2(inpF[r0 * 49 + k0], inpF[r0 * 49 + k0 + 1]);
            hi.y = pack_h2(inpF[(r0 + 8) * 49 + k0], inpF[(r0 + 8) * 49 + k0 + 1]);
            hi.z = pack_h2(inpF[r0 * 49 + k0 + 8], inpF[r0 * 49 + k0 + 9]);
            hi.w = pack_h2(inpF[(r0 + 8) * 49 + k0 + 8], inpF[(r0 + 8) * 49 + k0 + 9]);
            SHi[(kc * NRB + rbs) * 32 + lane] = hi;
        }
    }
    __syncthreads();

    float C4[NRB][4][4];
    float C2[NRB][2][4];

    // ---- L1: S(K=48) x W0 -> h1 (N=256) -> A --------------------------------
    mma_layer<3, 4, 16>(SHi, WL1, wid * 4, C4);
    epi_region<4, true>(C4, b0p, wid * 4, AHiW);
    __syncthreads();

    // ---- L2: A(K=256) x W1 -> h2 (N=256) -> A (in place) --------------------
    mma_layer<16, 4, 16>(AHi, WL2, wid * 4, C4);
    __syncthreads();
    epi_region<4, true>(C4, b1p, wid * 4, AHiW);
    __syncthreads();

    // ---- L3 (k-split): A(K=256) x W2 -> pred (N=32) -> P --------------------
    mma_part(AHi, WL3, wid & 1, (wid >> 1) * 4, 4, 2, C2);
    __syncthreads();                     // all reads of A done
    store_part(scr4, wid, C2);
    __syncthreads();
    if (wid < 2) {
        reduce4(scr4, wid, C2);
        epi_region<2, false>(C2, b2p, wid * 2, PHiW);
    }
    __syncthreads();

    // ---- O0: P(K=32) x OW0 -> off-hidden (N=256) -> A ------------------------
    mma_layer<2, 4, 16>(PHi, WO0, wid * 4, C4);
    epi_region<4, true>(C4, ob0p, wid * 4, AHiW);
    __syncthreads();

    // ---- O1 (k-split): A(K=256) x OW1 -> offsets; R0 overlaps ----------------
    mma_part(AHi, WO1, 0, wid * 2, 2, 1, C2);
    __syncthreads();                     // all reads of A done
    store_part(scr4, wid, C2);
    __syncthreads();
    if (wid == 0) {
        float o[NRB][4];
#pragma unroll
        for (int rb = 0; rb < NRB; ++rb) {
            int i = rb * 2;
            float4 acc = scr4[(i * 8 + 0) * 32 + lane];
#pragma unroll
            for (int s = 1; s < 8; ++s) {
                float4 v = scr4[(i * 8 + s) * 32 + lane];
                acc.x += v.x; acc.y += v.y; acc.z += v.z; acc.w += v.w;
            }
            o[rb][0] = acc.x; o[rb][1] = acc.y; o[rb][2] = acc.z; o[rb][3] = acc.w;
        }
        if ((lane & 3) == 0) {
            float o0 = __ldg(ob1p + 0), o1 = __ldg(ob1p + 1);
#pragma unroll
            for (int rb = 0; rb < NRB; ++rb) {
                int row = rb * 16 + (lane >> 2);
                offs[row * 2 + 0] = o[rb][0] + o0;
                offs[row * 2 + 1] = o[rb][1] + o1;
                offs[(row + 8) * 2 + 0] = o[rb][2] + o0;
                offs[(row + 8) * 2 + 1] = o[rb][3] + o1;
            }
        }
    }
    // R0 mma overlaps with warp 0's reduction (reads only P-fragments)
    mma_layer<2, 4, 16>(PHi, WR0, wid * 4, C4);
    __syncthreads();                     // offs written; scratch consumed
    epi_region<4, true>(C4, rb0p, wid * 4, AHiW);
    __syncthreads();

    // ---- R1 (k-split): A(K=256) x RW1 -> routing (N=32) -> routs fp32 --------
    mma_part(AHi, WR1, wid & 1, (wid >> 1) * 4, 4, 2, C2);
    __syncthreads();                     // all reads of A done
    store_part(scr4, wid, C2);
    __syncthreads();
    if (wid < 2) {
        reduce4(scr4, wid, C2);
        const int q = (lane & 3) * 2;
#pragma unroll
        for (int j = 0; j < 2; ++j) {
            int nc = wid * 2 + j;
            float bb0 = __ldg(rb1p + nc * 8 + q);
            float bb1 = __ldg(rb1p + nc * 8 + q + 1);
#pragma unroll
            for (int rb = 0; rb < NRB; ++rb) {
                int row = rb * 16 + (lane >> 2);
                routs[row * 33 + nc * 8 + q]     = C2[rb][j][0] + bb0;
                routs[row * 33 + nc * 8 + q + 1] = C2[rb][j][1] + bb1;
                routs[(row + 8) * 33 + nc * 8 + q]     = C2[rb][j][2] + bb0;
                routs[(row + 8) * 33 + nc * 8 + q + 1] = C2[rb][j][3] + bb1;
            }
        }
    }
    __syncthreads();

    // ---- Stage C: offset resample + modulate ---------------------------------
#pragma unroll 1
    for (int i = 0; i < 8; ++i) {
        int m = wid * 8 + i;
        int ql = qbase + m;
        int oy = ql >> 8, ox = ql & 255;
        float gy = (2.0f * oy + 1.0f) * (1.0f / 256.0f) - 1.0f;
        float gx = (2.0f * ox + 1.0f) * (1.0f / 256.0f) - 1.0f;
        float gx2 = gx + offs[m * 2 + 0];
        float gy2 = gy + offs[m * 2 + 1];
        int ix0, iy0;
        float wx[4], wy[4];
        prep_axis(gx2, ix0, wx);
        prep_axis(gy2, iy0, wy);
        float v = sample_c(xb, lane, ix0, iy0, wx, wy);
        outst[lane * 65 + m] = v * (1.0f + routs[m * 33 + lane]);
    }
    __syncthreads();

    // ---- writeout -------------------------------------------------------------
    {
        int c = tid >> 3;
        int part = tid & 7;
        const float* src = outst + c * 65 + part * 8;
        float* dst = out + ((size_t)(b * Cn + c)) * QPB + qbase + part * 8;
        *reinterpret_cast<float4*>(dst) =
            make_float4(src[0], src[1], src[2], src[3]);
        *reinterpret_cast<float4*>(dst + 4) =
            make_float4(src[4], src[5], src[6], src[7]);
    }
}

// ===========================================================================
// kernel_launch — 2 launches: setup (xt + prep), fused
// ===========================================================================
extern "C" void kernel_launch(void* const* d_in, const int* in_sizes, int n_in,
                              void* d_out, int out_size) {
    const float* x   = (const float*)d_in[0];
    const float* w0  = (const float*)d_in[1];
    const float* b0  = (const float*)d_in[2];
    const float* w1  = (const float*)d_in[3];
    const float* b1  = (const float*)d_in[4];
    const float* w2  = (const float*)d_in[5];
    const float* b2  = (const float*)d_in[6];
    const float* rw0 = (const float*)d_in[7];
    const float* rb0 = (const float*)d_in[8];
    const float* rw1 = (const float*)d_in[9];
    const float* rb1 = (const float*)d_in[10];
    const float* ow0 = (const float*)d_in[11];
    const float* ob0 = (const float*)d_in[12];
    const float* ow1 = (const float*)d_in[13];
    const float* ob1 = (const float*)d_in[14];
    float* out = (float*)d_out;

    setup_kernel<<<dim3(512, 8), 256>>>(x, w0, w1, w2, rw0, rw1, ow0, ow1);

    cudaFuncSetAttribute(fused_kernel,
                         cudaFuncAttributeMaxDynamicSharedMemorySize, SMEM_BYTES);
    fused_kernel<<<NCTA, 256, SMEM_BYTES>>>(b0, b1, b2, rb0, rb1, ob0, ob1, out);
}

// round 13
// speedup vs baseline: 1.0218x; 1.0218x over previous
#include <cuda_runtime.h>
#include <cuda_fp16.h>
#include <cstdint>

// ===========================================================================
// Problem constants (fixed: B=4, C=32, H=W=128, scale=2)
// ===========================================================================
#define Bn    4
#define Cn    32
#define Hn    128
#define Wn    128
#define QPB   65536
#define NQ    (Bn * QPB)
#define MT    32                   // queries per CTA
#define NCTA  (NQ / MT)            // 8192
#define NRB   2                    // row-blocks (16 rows) per CTA

// ===========================================================================
// Global scratch
// ===========================================================================
__device__ float g_xt[Bn * Hn * Wn * Cn];   // channels-last x

// Weight images: B-fragment-packed fp16.
#define WOFF_L1  0u          // KC=3,  NPT=16 -> 24576
#define WOFF_L2  24576u      // KC=16, NPT=16 -> 131072
#define WOFF_L3  155648u     // KC=16, NPT=2  -> 16384
#define WOFF_R0  172032u     // KC=2,  NPT=16 -> 16384
#define WOFF_R1  188416u     // KC=16, NPT=2  -> 16384
#define WOFF_O0  204800u     // KC=2,  NPT=16 -> 16384
#define WOFF_O1  221184u     // KC=16, NPT=1  -> 8192
#define WIMG_TOTAL 229376u
__device__ __align__(16) unsigned char g_wimg[WIMG_TOTAL];

// ===========================================================================
// Setup kernel: y==0 -> transpose x; y>=1 -> weight prep for layer y-1.
// ===========================================================================
__global__ void setup_kernel(const float* __restrict__ x,
                             const float* __restrict__ w0, const float* __restrict__ w1,
                             const float* __restrict__ w2, const float* __restrict__ rw0,
                             const float* __restrict__ rw1, const float* __restrict__ ow0,
                             const float* __restrict__ ow1) {
    const int tid = threadIdx.x;
    if (blockIdx.y == 0) {
        __shared__ float s[Cn][Wn + 1];
        const int by = blockIdx.x;      // 0..511
#pragma unroll
        for (int it = 0; it < 16; ++it) {
            int idx = tid + it * 256;
            int c = idx >> 7, xc = idx & 127;
            int b = by >> 7, y = by & 127;
            s[c][xc] = x[((b * Cn + c) * Hn + y) * Wn + xc];
        }
        __syncthreads();
#pragma unroll
        for (int it = 0; it < 16; ++it) {
            int idx = tid + it * 256;
            int xc = idx >> 5, c = idx & 31;
            g_xt[(by * Wn + xc) * Cn + c] = s[c][xc];
        }
        return;
    }
    const float* W;
    int Kdim, Ndim, Kt, Nt;
    uint32_t dstOff;
    switch (blockIdx.y - 1) {
        case 0: W = w0;  Kdim = 36;  Ndim = 256; Kt = 48;  Nt = 256; dstOff = WOFF_L1; break;
        case 1: W = w1;  Kdim = 256; Ndim = 256; Kt = 256; Nt = 256; dstOff = WOFF_L2; break;
        case 2: W = w2;  Kdim = 256; Ndim = 32;  Kt = 256; Nt = 32;  dstOff = WOFF_L3; break;
        case 3: W = rw0; Kdim = 32;  Ndim = 256; Kt = 32;  Nt = 256; dstOff = WOFF_R0; break;
        case 4: W = rw1; Kdim = 256; Ndim = 32;  Kt = 256; Nt = 32;  dstOff = WOFF_R1; break;
        case 5: W = ow0; Kdim = 32;  Ndim = 256; Kt = 32;  Nt = 256; dstOff = WOFF_O0; break;
        default: W = ow1; Kdim = 256; Ndim = 2;  Kt = 256; Nt = 16;  dstOff = WOFF_O1; break;
    }
    int idx = blockIdx.x * 256 + tid;
    if (idx >= Kt * Nt) return;
    int k = idx / Nt;
    int n = idx % Nt;
    float w = (k < Kdim && n < Ndim) ? W[k * Ndim + n] : 0.0f;
    __half hb = __float2half_rn(w);
    int kc = k >> 4, ki = k & 15;
    int nc = n >> 3, ni = n & 7;
    int npair = nc >> 1;
    int lane = ni * 4 + ((ki & 7) >> 1);
    int word = (ki >> 3) + (nc & 1) * 2;
    int half = ki & 1;
    uint32_t off = (uint32_t)(((kc * (Nt >> 4) + npair) * 32 + lane) * 16 +
                              word * 4 + half * 2);
    *reinterpret_cast<unsigned short*>(g_wimg + dstOff + off) = __half_as_ushort(hb);
}

// ===========================================================================
// Bicubic helpers (torch aten, A=-0.75)
// ===========================================================================
__device__ __forceinline__ void prep_axis(float g, int& i0, float w[4]) {
    float p = ((g + 1.0f) * 128.0f - 1.0f) * 0.5f;
    float fp = floorf(p);
    i0 = (int)fp;
    float t = p - fp;
    const float A = -0.75f;
    float xx = t + 1.0f;
    w[0] = ((A * xx - 5.0f * A) * xx + 8.0f * A) * xx - 4.0f * A;
    w[1] = ((A + 2.0f) * t - (A + 3.0f)) * t * t + 1.0f;
    float s = 1.0f - t;
    w[2] = ((A + 2.0f) * s - (A + 3.0f)) * s * s + 1.0f;
    w[3] = 1.0f - w[0] - w[1] - w[2];
}

__device__ __forceinline__ float sample_c(const float* __restrict__ xb, int lane,
                                          int ix0, int iy0,
                                          const float* wx, const float* wy) {
    float acc = 0.0f;
#pragma unroll
    for (int i = 0; i < 4; ++i) {
        int yi = iy0 - 1 + i;
        if ((unsigned)yi < 128u) {
            const float* rp = xb + yi * (Wn * Cn) + lane;
            float r = 0.0f;
#pragma unroll
            for (int j = 0; j < 4; ++j) {
                int xj = ix0 - 1 + j;
                if ((unsigned)xj < 128u) r = fmaf(wx[j], __ldg(rp + xj * Cn), r);
            }
            acc = fmaf(wy[i], r, acc);
        }
    }
    return acc;
}

// packed fp16x2 (v1 in high half, v0 in low half)
__device__ __forceinline__ uint32_t pack_h2(float v0, float v1) {
    __half2 h = __floats2half2_rn(v0, v1);
    return *reinterpret_cast<uint32_t*>(&h);
}

// ===========================================================================
// mma.sync m16n8k16 fp16
// ===========================================================================
__device__ __forceinline__ void mma_f16(float* c, const uint4& a,
                                        uint32_t b0, uint32_t b1) {
    asm("mma.sync.aligned.m16n8k16.row.col.f32.f16.f16.f32 "
        "{%0,%1,%2,%3},{%4,%5,%6,%7},{%8,%9},{%0,%1,%2,%3};"
        : "+f"(c[0]), "+f"(c[1]), "+f"(c[2]), "+f"(c[3])
        : "r"(a.x), "r"(a.y), "r"(a.z), "r"(a.w), "r"(b0), "r"(b1));
}

// Wide K-loop over BOTH 16-row blocks, single-term: C += A*B.
template <int KC, int NC, int NPT>
__device__ __forceinline__ void mma_layer(const uint4* __restrict__ aHi,
                                          const uint4* __restrict__ bHi,
                                          int nc0, float C[2][NC][4]) {
    const int lane = threadIdx.x & 31;
#pragma unroll
    for (int r = 0; r < 2; ++r)
#pragma unroll
        for (int j = 0; j < NC; ++j)
#pragma unroll
            for (int t = 0; t < 4; ++t) C[r][j][t] = 0.0f;
    const int npair0 = nc0 >> 1;
#pragma unroll 1
    for (int kc = 0; kc < KC; ++kc) {
        uint4 ah0 = aHi[(kc * NRB + 0) * 32 + lane];
        uint4 ah1 = aHi[(kc * NRB + 1) * 32 + lane];
#pragma unroll
        for (int p = 0; p < NC / 2; ++p) {
            uint4 bh = __ldg(bHi + (kc * NPT + npair0 + p) * 32 + lane);
            mma_f16(C[0][2 * p], ah0, bh.x, bh.y);
            mma_f16(C[1][2 * p], ah1, bh.x, bh.y);
            mma_f16(C[0][2 * p + 1], ah0, bh.z, bh.w);
            mma_f16(C[1][2 * p + 1], ah1, bh.z, bh.w);
        }
    }
}

// Partial K-slice, both n-chunks of one npair: kc in [kc0, kc0+kcn).
__device__ __forceinline__ void mma_part(const uint4* __restrict__ aHi,
                                         const uint4* __restrict__ bHi,
                                         int npair0, int kc0, int kcn, int NPT,
                                         float C[2][2][4]) {
    const int lane = threadIdx.x & 31;
#pragma unroll
    for (int r = 0; r < 2; ++r)
#pragma unroll
        for (int j = 0; j < 2; ++j)
#pragma unroll
            for (int t = 0; t < 4; ++t) C[r][j][t] = 0.0f;
#pragma unroll 1
    for (int kc = kc0; kc < kc0 + kcn; ++kc) {
        uint4 ah0 = aHi[(kc * NRB + 0) * 32 + lane];
        uint4 ah1 = aHi[(kc * NRB + 1) * 32 + lane];
        uint4 bh = __ldg(bHi + (kc * NPT + npair0) * 32 + lane);
        mma_f16(C[0][0], ah0, bh.x, bh.y);
        mma_f16(C[1][0], ah1, bh.x, bh.y);
        mma_f16(C[0][1], ah0, bh.z, bh.w);
        mma_f16(C[1][1], ah1, bh.z, bh.w);
    }
}

// Partial K-slice, FIRST n-chunk only (for O1: real N=2).
__device__ __forceinline__ void mma_part1(const uint4* __restrict__ aHi,
                                          const uint4* __restrict__ bHi,
                                          int kc0, int kcn,
                                          float C[2][4]) {
    const int lane = threadIdx.x & 31;
#pragma unroll
    for (int r = 0; r < 2; ++r)
#pragma unroll
        for (int t = 0; t < 4; ++t) C[r][t] = 0.0f;
#pragma unroll 1
    for (int kc = kc0; kc < kc0 + kcn; ++kc) {
        uint4 ah0 = aHi[(kc * NRB + 0) * 32 + lane];
        uint4 ah1 = aHi[(kc * NRB + 1) * 32 + lane];
        uint4 bh = __ldg(bHi + kc * 32 + lane);   // NPT=1, npair0=0
        mma_f16(C[0], ah0, bh.x, bh.y);
        mma_f16(C[1], ah1, bh.x, bh.y);
    }
}

// Epilogue: bias(+ReLU), pack fp16 A fragments for the next layer.
template <int NC, bool RELU>
__device__ __forceinline__ void epi_region(float C[2][NC][4],
                                           const float* __restrict__ biasp,
                                           int nc0, uint32_t* dHi) {
    const int lane = threadIdx.x & 31;
    const int q = (lane & 3) * 2;
#pragma unroll
    for (int j = 0; j < NC; ++j) {
        int nc = nc0 + j;
        int kc = nc >> 1, odd = nc & 1;
        float b0 = __ldg(biasp + nc * 8 + q);
        float b1 = __ldg(biasp + nc * 8 + q + 1);
#pragma unroll
        for (int r = 0; r < 2; ++r) {
            float v0 = C[r][j][0] + b0, v1 = C[r][j][1] + b1;
            float v2 = C[r][j][2] + b0, v3 = C[r][j][3] + b1;
            if (RELU) {
                v0 = fmaxf(v0, 0.f); v1 = fmaxf(v1, 0.f);
                v2 = fmaxf(v2, 0.f); v3 = fmaxf(v3, 0.f);
            }
            int base = ((kc * NRB + r) * 32 + lane) * 4 + odd * 2;
            dHi[base] = pack_h2(v0, v1);
            dHi[base + 1] = pack_h2(v2, v3);
        }
    }
}

// ===========================================================================
// SMEM layout (bytes) — total 48640; 4 CTAs/SM
// ===========================================================================
#define SM_INPF  0          // fp32 [32][49] = 6272 (reused as routs [32][33])
#define SM_SHI   6272       // inp frags: 3*2*512 = 3072
#define SM_PHI   9344       // pred frags: 2*2*512 = 2048
#define SM_AHI   11392      // act frags A: 16*2*512 = 16384 (doubles as scratch)
#define SM_AH2   27776      // act frags B (rout-hidden): 16384
#define SM_OFFS  44160      // fp32 [32][2] = 256
#define SM_OUT   44416      // fp32 [32][33] = 4224
#define SMEM_BYTES 48640

// ===========================================================================
// Fused kernel: 32 queries per CTA, 8 warps, 4 CTAs/SM.
// Wide layers: warp = unique 32 N-cols. Narrow layers: k-split; O1/R1 concurrent.
// ===========================================================================
__global__ __launch_bounds__(256, 4) void fused_kernel(
    const float* __restrict__ b0p, const float* __restrict__ b1p,
    const float* __restrict__ b2p, const float* __restrict__ rb0p,
    const float* __restrict__ rb1p, const float* __restrict__ ob0p,
    const float* __restrict__ ob1p, float* __restrict__ out) {
    extern __shared__ __align__(16) unsigned char smraw[];
    float* inpF = reinterpret_cast<float*>(smraw + SM_INPF);
    uint4* SHi = reinterpret_cast<uint4*>(smraw + SM_SHI);
    uint4* PHi = reinterpret_cast<uint4*>(smraw + SM_PHI);
    uint4* AHi = reinterpret_cast<uint4*>(smraw + SM_AHI);
    uint4* AH2 = reinterpret_cast<uint4*>(smraw + SM_AH2);
    uint32_t* PHiW = reinterpret_cast<uint32_t*>(PHi);
    uint32_t* AHiW = reinterpret_cast<uint32_t*>(AHi);
    uint32_t* AH2W = reinterpret_cast<uint32_t*>(AH2);
    float4* scr4 = reinterpret_cast<float4*>(smraw + SM_AHI);  // narrow scratch
    float* offs  = reinterpret_cast<float*>(smraw + SM_OFFS);
    float* outst = reinterpret_cast<float*>(smraw + SM_OUT);
    float* routs = inpF;   // reuse after L1 staging

    const int tid = threadIdx.x;
    const int lane = tid & 31;
    const int wid = tid >> 5;

    const int q0 = blockIdx.x * MT;
    const int b = q0 >> 16;
    const int qbase = q0 & (QPB - 1);
    const float* xb = g_xt + b * (Hn * Wn * Cn);

    const uint4* WL1 = (const uint4*)(g_wimg + WOFF_L1);
    const uint4* WL2 = (const uint4*)(g_wimg + WOFF_L2);
    const uint4* WL3 = (const uint4*)(g_wimg + WOFF_L3);
    const uint4* WR0 = (const uint4*)(g_wimg + WOFF_R0);
    const uint4* WR1 = (const uint4*)(g_wimg + WOFF_R1);
    const uint4* WO0 = (const uint4*)(g_wimg + WOFF_O0);
    const uint4* WO1 = (const uint4*)(g_wimg + WOFF_O1);

    // ---- Stage A: sampling -> inpF [32][49] --------------------------------
#pragma unroll 1
    for (int i = 0; i < 4; ++i) {
        int m = wid * 4 + i;
        int ql = qbase + m;
        int oy = ql >> 8, ox = ql & 255;
        float gy = (2.0f * oy + 1.0f) * (1.0f / 256.0f) - 1.0f;
        float gx = (2.0f * ox + 1.0f) * (1.0f / 256.0f) - 1.0f;
        int ix0, iy0;
        float wx[4], wy[4];
        prep_axis(gx, ix0, wx);
        prep_axis(gy, iy0, wy);
        inpF[m * 49 + lane] = sample_c(xb, lane, ix0, iy0, wx, wy);
        if (lane == 0) {
            float syw = 0.f, sy = 0.f, sxw = 0.f, sx = 0.f;
#pragma unroll
            for (int ii = 0; ii < 4; ++ii) {
                int yi = iy0 - 1 + ii;
                if ((unsigned)yi < 128u) {
                    float yco = (2.0f * yi + 1.0f) * (1.0f / 128.0f) - 1.0f;
                    syw += wy[ii]; sy = fmaf(wy[ii], yco, sy);
                }
            }
#pragma unroll
            for (int jj = 0; jj < 4; ++jj) {
                int xj = ix0 - 1 + jj;
                if ((unsigned)xj < 128u) {
                    float xco = (2.0f * xj + 1.0f) * (1.0f / 128.0f) - 1.0f;
                    sxw += wx[jj]; sx = fmaf(wx[jj], xco, sx);
                }
            }
            inpF[m * 49 + 32] = (gy - sy * sxw) * 128.0f;
            inpF[m * 49 + 33] = (gx - sx * syw) * 128.0f;
            float rc = (ql < 2) ? 1.0f : 128.0f;   // faithful cell quirk
            inpF[m * 49 + 34] = rc;
            inpF[m * 49 + 35] = rc;
        }
        if (lane >= 4 && lane < 16) inpF[m * 49 + 32 + lane] = 0.0f;  // pad 36..47
    }
    __syncthreads();

    // ---- Stage S frags: inpF -> S (A-fragment fp16, K=48) -------------------
    if (wid < 6) {
        int kc = wid >> 1, rbs = wid & 1;
        int r0 = rbs * 16 + (lane >> 2);
        int k0 = kc * 16 + (lane & 3) * 2;
        uint4 hi;
        hi.x = pack_h2(inpF[r0 * 49 + k0], inpF[r0 * 49 + k0 + 1]);
        hi.y = pack_h2(inpF[(r0 + 8) * 49 + k0], inpF[(r0 + 8) * 49 + k0 + 1]);
        hi.z = pack_h2(inpF[r0 * 49 + k0 + 8], inpF[r0 * 49 + k0 + 9]);
        hi.w = pack_h2(inpF[(r0 + 8) * 49 + k0 + 8], inpF[(r0 + 8) * 49 + k0 + 9]);
        SHi[(kc * NRB + rbs) * 32 + lane] = hi;
    }
    __syncthreads();

    float C4[2][4][4];
    float C2[2][2][4];

    // ---- L1: S(K=48) x W0 -> h1 (N=256) -> A --------------------------------
    mma_layer<3, 4, 16>(SHi, WL1, wid * 4, C4);
    epi_region<4, true>(C4, b0p, wid * 4, AHiW);
    __syncthreads();

    // ---- L2: A(K=256) x W1 -> h2 (N=256) -> A (in place) --------------------
    mma_layer<16, 4, 16>(AHi, WL2, wid * 4, C4);
    __syncthreads();
    epi_region<4, true>(C4, b1p, wid * 4, AHiW);
    __syncthreads();

    // ---- L3 (k-split): A(K=256) x W2 -> pred (N=32) -> P --------------------
    mma_part(AHi, WL3, wid & 1, (wid >> 1) * 4, 4, 2, C2);
    __syncthreads();                     // all reads of A done
    {   // store partials: rows 0..31 of scr region
        const int llane = lane;
#pragma unroll
        for (int r = 0; r < 2; ++r)
#pragma unroll
            for (int j = 0; j < 2; ++j) {
                int i = r * 2 + j;
                scr4[(i * 8 + wid) * 32 + llane] =
                    make_float4(C2[r][j][0], C2[r][j][1], C2[r][j][2], C2[r][j][3]);
            }
    }
    __syncthreads();
    if (wid < 2) {
        // reduce 4 k-slices (slices wid, wid+2, wid+4, wid+6)
#pragma unroll
        for (int i = 0; i < 4; ++i) {
            float4 a = scr4[(i * 8 + wid) * 32 + lane];
            float4 bq = scr4[(i * 8 + 2 + wid) * 32 + lane];
            float4 c = scr4[(i * 8 + 4 + wid) * 32 + lane];
            float4 d = scr4[(i * 8 + 6 + wid) * 32 + lane];
            C2[i >> 1][i & 1][0] = (a.x + bq.x) + (c.x + d.x);
            C2[i >> 1][i & 1][1] = (a.y + bq.y) + (c.y + d.y);
            C2[i >> 1][i & 1][2] = (a.z + bq.z) + (c.z + d.z);
            C2[i >> 1][i & 1][3] = (a.w + bq.w) + (c.w + d.w);
        }
        epi_region<2, false>(C2, b2p, wid * 2, PHiW);
    }
    __syncthreads();

    // ---- O0 + R0 fused phase: P(K=32) x {OW0, RW0} -> AHi, AH2 ---------------
    mma_layer<2, 4, 16>(PHi, WO0, wid * 4, C4);
    epi_region<4, true>(C4, ob0p, wid * 4, AHiW);
    mma_layer<2, 4, 16>(PHi, WR0, wid * 4, C4);
    epi_region<4, true>(C4, rb0p, wid * 4, AH2W);
    __syncthreads();

    // ---- O1 (warps 0-3, reads AHi) ∥ R1 (warps 4-7, reads AH2) ---------------
    float C2b[2][4];
    if (wid < 4) {
        mma_part1(AHi, WO1, wid * 4, 4, C2b);
    } else {
        int p = (wid - 4) >> 1;
        int slice = (wid - 4) & 1;
        mma_part(AH2, WR1, p, slice * 8, 8, 2, C2);
    }
    __syncthreads();                     // all reads of AHi/AH2 done
    // store partials into scr4 (aliases AHi):
    //   R1: rows [p*8 + i*2 + slice], i=r*2+j (0..3)  -> rows 0..15
    //   O1: rows [16 + r*4 + wid], r=0..1             -> rows 16..23
    if (wid < 4) {
#pragma unroll
        for (int r = 0; r < 2; ++r)
            scr4[(16 + r * 4 + wid) * 32 + lane] =
                make_float4(C2b[r][0], C2b[r][1], C2b[r][2], C2b[r][3]);
    } else {
        int p = (wid - 4) >> 1;
        int slice = (wid - 4) & 1;
#pragma unroll
        for (int r = 0; r < 2; ++r)
#pragma unroll
            for (int j = 0; j < 2; ++j) {
                int i = r * 2 + j;
                scr4[(p * 8 + i * 2 + slice) * 32 + lane] =
                    make_float4(C2[r][j][0], C2[r][j][1], C2[r][j][2], C2[r][j][3]);
            }
    }
    __syncthreads();
    if (wid < 2) {
        // reduce R1 npair=wid (2 slices) -> routs
        const int q = (lane & 3) * 2;
#pragma unroll
        for (int i = 0; i < 4; ++i) {
            float4 a = scr4[(wid * 8 + i * 2 + 0) * 32 + lane];
            float4 bq = scr4[(wid * 8 + i * 2 + 1) * 32 + lane];
            C2[i >> 1][i & 1][0] = a.x + bq.x;
            C2[i >> 1][i & 1][1] = a.y + bq.y;
            C2[i >> 1][i & 1][2] = a.z + bq.z;
            C2[i >> 1][i & 1][3] = a.w + bq.w;
        }
#pragma unroll
        for (int j = 0; j < 2; ++j) {
            int nc = wid * 2 + j;
            float bb0 = __ldg(rb1p + nc * 8 + q);
            float bb1 = __ldg(rb1p + nc * 8 + q + 1);
#pragma unroll
            for (int r = 0; r < 2; ++r) {
                int row = r * 16 + (lane >> 2);
                routs[row * 33 + nc * 8 + q]     = C2[r][j][0] + bb0;
                routs[row * 33 + nc * 8 + q + 1] = C2[r][j][1] + bb1;
                routs[(row + 8) * 33 + nc * 8 + q]     = C2[r][j][2] + bb0;
                routs[(row + 8) * 33 + nc * 8 + q + 1] = C2[r][j][3] + bb1;
            }
        }
    } else if (wid == 2) {
        // reduce O1 (4 slices per r) -> offs
        float o[2][4];
#pragma unroll
        for (int r = 0; r < 2; ++r) {
            float4 acc = scr4[(16 + r * 4 + 0) * 32 + lane];
#pragma unroll
            for (int s = 1; s < 4; ++s) {
                float4 v = scr4[(16 + r * 4 + s) * 32 + lane];
                acc.x += v.x; acc.y += v.y; acc.z += v.z; acc.w += v.w;
            }
            o[r][0] = acc.x; o[r][1] = acc.y; o[r][2] = acc.z; o[r][3] = acc.w;
        }
        if ((lane & 3) == 0) {
            float o0 = __ldg(ob1p + 0), o1 = __ldg(ob1p + 1);
#pragma unroll
            for (int r = 0; r < 2; ++r) {
                int row = r * 16 + (lane >> 2);
                offs[row * 2 + 0] = o[r][0] + o0;
                offs[row * 2 + 1] = o[r][1] + o1;
                offs[(row + 8) * 2 + 0] = o[r][2] + o0;
                offs[(row + 8) * 2 + 1] = o[r][3] + o1;
            }
        }
    }
    __syncthreads();

    // ---- Stage C: offset resample + modulate ---------------------------------
#pragma unroll 1
    for (int i = 0; i < 4; ++i) {
        int m = wid * 4 + i;
        int ql = qbase + m;
        int oy = ql >> 8, ox = ql & 255;
        float gy = (2.0f * oy + 1.0f) * (1.0f / 256.0f) - 1.0f;
        float gx = (2.0f * ox + 1.0f) * (1.0f / 256.0f) - 1.0f;
        float gx2 = gx + offs[m * 2 + 0];
        float gy2 = gy + offs[m * 2 + 1];
        int ix0, iy0;
        float wx[4], wy[4];
        prep_axis(gx2, ix0, wx);
        prep_axis(gy2, iy0, wy);
        float v = sample_c(xb, lane, ix0, iy0, wx, wy);
        outst[lane * 33 + m] = v * (1.0f + routs[m * 33 + lane]);
    }
    __syncthreads();

    // ---- writeout -------------------------------------------------------------
    {
        int c = tid >> 3;
        int part = tid & 7;
        const float* src = outst + c * 33 + part * 4;
        float* dst = out + ((size_t)(b * Cn + c)) * QPB + qbase + part * 4;
        *reinterpret_cast<float4*>(dst) =
            make_float4(src[0], src[1], src[2], src[3]);
    }
}

// ===========================================================================
// kernel_launch — 2 launches: setup (xt + prep), fused
// ===========================================================================
extern "C" void kernel_launch(void* const* d_in, const int* in_sizes, int n_in,
                              void* d_out, int out_size) {
    const float* x   = (const float*)d_in[0];
    const float* w0  = (const float*)d_in[1];
    const float* b0  = (const float*)d_in[2];
    const float* w1  = (const float*)d_in[3];
    const float* b1  = (const float*)d_in[4];
    const float* w2  = (const float*)d_in[5];
    const float* b2  = (const float*)d_in[6];
    const float* rw0 = (const float*)d_in[7];
    const float* rb0 = (const float*)d_in[8];
    const float* rw1 = (const float*)d_in[9];
    const float* rb1 = (const float*)d_in[10];
    const float* ow0 = (const float*)d_in[11];
    const float* ob0 = (const float*)d_in[12];
    const float* ow1 = (const float*)d_in[13];
    const float* ob1 = (const float*)d_in[14];
    float* out = (float*)d_out;

    setup_kernel<<<dim3(512, 8), 256>>>(x, w0, w1, w2, rw0, rw1, ow0, ow1);

    cudaFuncSetAttribute(fused_kernel,
                         cudaFuncAttributeMaxDynamicSharedMemorySize, SMEM_BYTES);
    fused_kernel<<<NCTA, 256, SMEM_BYTES>>>(b0, b1, b2, rb0, rb1, ob0, ob1, out);
}

// round 14
// speedup vs baseline: 1.3738x; 1.3445x over previous
#include <cuda_runtime.h>
#include <cuda_fp16.h>
#include <cstdint>

// ===========================================================================
// Problem constants (fixed: B=4, C=32, H=W=128, scale=2)
// ===========================================================================
#define Bn    4
#define Cn    32
#define Hn    128
#define Wn    128
#define QPB   65536
#define NQ    (Bn * QPB)
#define MT    32                   // queries per CTA
#define NCTA  (NQ / MT)            // 8192
#define NRB   2                    // row-blocks (16 rows) per CTA

// ===========================================================================
// Global scratch
// ===========================================================================
__device__ float g_xt[Bn * Hn * Wn * Cn];   // channels-last x

// Weight images: B-fragment-packed fp16.
#define WOFF_L1  0u          // KC=3,  NPT=16 -> 24576
#define WOFF_L2  24576u      // KC=16, NPT=16 -> 131072
#define WOFF_L3  155648u     // KC=16, NPT=2  -> 16384
#define WOFF_R0  172032u     // KC=2,  NPT=16 -> 16384
#define WOFF_R1  188416u     // KC=16, NPT=2  -> 16384
#define WOFF_O0  204800u     // KC=2,  NPT=16 -> 16384
#define WOFF_O1  221184u     // KC=16, NPT=1  -> 8192
#define WIMG_TOTAL 229376u
__device__ __align__(16) unsigned char g_wimg[WIMG_TOTAL];

// ===========================================================================
// Setup kernel: y==0 -> transpose x; y>=1 -> weight prep for layer y-1.
// ===========================================================================
__global__ void setup_kernel(const float* __restrict__ x,
                             const float* __restrict__ w0, const float* __restrict__ w1,
                             const float* __restrict__ w2, const float* __restrict__ rw0,
                             const float* __restrict__ rw1, const float* __restrict__ ow0,
                             const float* __restrict__ ow1) {
    const int tid = threadIdx.x;
    if (blockIdx.y == 0) {
        __shared__ float s[Cn][Wn + 1];
        const int by = blockIdx.x;      // 0..511
#pragma unroll
        for (int it = 0; it < 16; ++it) {
            int idx = tid + it * 256;
            int c = idx >> 7, xc = idx & 127;
            int b = by >> 7, y = by & 127;
            s[c][xc] = x[((b * Cn + c) * Hn + y) * Wn + xc];
        }
        __syncthreads();
#pragma unroll
        for (int it = 0; it < 16; ++it) {
            int idx = tid + it * 256;
            int xc = idx >> 5, c = idx & 31;
            g_xt[(by * Wn + xc) * Cn + c] = s[c][xc];
        }
        return;
    }
    const float* W;
    int Kdim, Ndim, Kt, Nt;
    uint32_t dstOff;
    switch (blockIdx.y - 1) {
        case 0: W = w0;  Kdim = 36;  Ndim = 256; Kt = 48;  Nt = 256; dstOff = WOFF_L1; break;
        case 1: W = w1;  Kdim = 256; Ndim = 256; Kt = 256; Nt = 256; dstOff = WOFF_L2; break;
        case 2: W = w2;  Kdim = 256; Ndim = 32;  Kt = 256; Nt = 32;  dstOff = WOFF_L3; break;
        case 3: W = rw0; Kdim = 32;  Ndim = 256; Kt = 32;  Nt = 256; dstOff = WOFF_R0; break;
        case 4: W = rw1; Kdim = 256; Ndim = 32;  Kt = 256; Nt = 32;  dstOff = WOFF_R1; break;
        case 5: W = ow0; Kdim = 32;  Ndim = 256; Kt = 32;  Nt = 256; dstOff = WOFF_O0; break;
        default: W = ow1; Kdim = 256; Ndim = 2;  Kt = 256; Nt = 16;  dstOff = WOFF_O1; break;
    }
    int idx = blockIdx.x * 256 + tid;
    if (idx >= Kt * Nt) return;
    int k = idx / Nt;
    int n = idx % Nt;
    float w = (k < Kdim && n < Ndim) ? W[k * Ndim + n] : 0.0f;
    __half hb = __float2half_rn(w);
    int kc = k >> 4, ki = k & 15;
    int nc = n >> 3, ni = n & 7;
    int npair = nc >> 1;
    int lane = ni * 4 + ((ki & 7) >> 1);
    int word = (ki >> 3) + (nc & 1) * 2;
    int half = ki & 1;
    uint32_t off = (uint32_t)(((kc * (Nt >> 4) + npair) * 32 + lane) * 16 +
                              word * 4 + half * 2);
    *reinterpret_cast<unsigned short*>(g_wimg + dstOff + off) = __half_as_ushort(hb);
}

// ===========================================================================
// Bicubic helpers (torch aten, A=-0.75)
// ===========================================================================
__device__ __forceinline__ void prep_axis(float g, int& i0, float w[4]) {
    float p = ((g + 1.0f) * 128.0f - 1.0f) * 0.5f;
    float fp = floorf(p);
    i0 = (int)fp;
    float t = p - fp;
    const float A = -0.75f;
    float xx = t + 1.0f;
    w[0] = ((A * xx - 5.0f * A) * xx + 8.0f * A) * xx - 4.0f * A;
    w[1] = ((A + 2.0f) * t - (A + 3.0f)) * t * t + 1.0f;
    float s = 1.0f - t;
    w[2] = ((A + 2.0f) * s - (A + 3.0f)) * s * s + 1.0f;
    w[3] = 1.0f - w[0] - w[1] - w[2];
}

// guarded (boundary) path
__device__ __forceinline__ float sample_slow(const float* __restrict__ xb, int lane,
                                             int ix0, int iy0,
                                             const float* wx, const float* wy) {
    float acc = 0.0f;
#pragma unroll
    for (int i = 0; i < 4; ++i) {
        int yi = iy0 - 1 + i;
        if ((unsigned)yi < 128u) {
            const float* rp = xb + yi * (Wn * Cn) + lane;
            float r = 0.0f;
#pragma unroll
            for (int j = 0; j < 4; ++j) {
                int xj = ix0 - 1 + j;
                if ((unsigned)xj < 128u) r = fmaf(wx[j], __ldg(rp + xj * Cn), r);
            }
            acc = fmaf(wy[i], r, acc);
        }
    }
    return acc;
}

// unguarded interior path (ix0 in [1,125], iy0 in [1,125]); warp-uniform branch
__device__ __forceinline__ float sample_c(const float* __restrict__ xb, int lane,
                                          int ix0, int iy0,
                                          const float* wx, const float* wy) {
    if ((unsigned)(ix0 - 1) <= 124u && (unsigned)(iy0 - 1) <= 124u) {
        const float* rp = xb + (iy0 - 1) * (Wn * Cn) + (ix0 - 1) * Cn + lane;
        float acc = 0.0f;
#pragma unroll
        for (int i = 0; i < 4; ++i) {
            float r = wx[0] * __ldg(rp);
            r = fmaf(wx[1], __ldg(rp + Cn), r);
            r = fmaf(wx[2], __ldg(rp + 2 * Cn), r);
            r = fmaf(wx[3], __ldg(rp + 3 * Cn), r);
            acc = fmaf(wy[i], r, acc);
            rp += Wn * Cn;
        }
        return acc;
    }
    return sample_slow(xb, lane, ix0, iy0, wx, wy);
}

// packed fp16x2 (v1 in high half, v0 in low half)
__device__ __forceinline__ uint32_t pack_h2(float v0, float v1) {
    __half2 h = __floats2half2_rn(v0, v1);
    return *reinterpret_cast<uint32_t*>(&h);
}

// ===========================================================================
// mma.sync m16n8k16 fp16
// ===========================================================================
__device__ __forceinline__ void mma_f16(float* c, const uint4& a,
                                        uint32_t b0, uint32_t b1) {
    asm("mma.sync.aligned.m16n8k16.row.col.f32.f16.f16.f32 "
        "{%0,%1,%2,%3},{%4,%5,%6,%7},{%8,%9},{%0,%1,%2,%3};"
        : "+f"(c[0]), "+f"(c[1]), "+f"(c[2]), "+f"(c[3])
        : "r"(a.x), "r"(a.y), "r"(a.z), "r"(a.w), "r"(b0), "r"(b1));
}

// Wide K-loop over BOTH 16-row blocks, single-term: C += A*B.
template <int KC, int NC, int NPT>
__device__ __forceinline__ void mma_layer(const uint4* __restrict__ aHi,
                                          const uint4* __restrict__ bHi,
                                          int nc0, float C[2][NC][4]) {
    const int lane = threadIdx.x & 31;
#pragma unroll
    for (int r = 0; r < 2; ++r)
#pragma unroll
        for (int j = 0; j < NC; ++j)
#pragma unroll
            for (int t = 0; t < 4; ++t) C[r][j][t] = 0.0f;
    const int npair0 = nc0 >> 1;
#pragma unroll 1
    for (int kc = 0; kc < KC; ++kc) {
        uint4 ah0 = aHi[(kc * NRB + 0) * 32 + lane];
        uint4 ah1 = aHi[(kc * NRB + 1) * 32 + lane];
#pragma unroll
        for (int p = 0; p < NC / 2; ++p) {
            uint4 bh = __ldg(bHi + (kc * NPT + npair0 + p) * 32 + lane);
            mma_f16(C[0][2 * p], ah0, bh.x, bh.y);
            mma_f16(C[1][2 * p], ah1, bh.x, bh.y);
            mma_f16(C[0][2 * p + 1], ah0, bh.z, bh.w);
            mma_f16(C[1][2 * p + 1], ah1, bh.z, bh.w);
        }
    }
}

// Partial K-slice for narrow (N<=32) layers: one npair, kc in [kc0, kc0+kcn).
__device__ __forceinline__ void mma_part(const uint4* __restrict__ aHi,
                                         const uint4* __restrict__ bHi,
                                         int npair0, int kc0, int kcn, int NPT,
                                         float C[2][2][4]) {
    const int lane = threadIdx.x & 31;
#pragma unroll
    for (int r = 0; r < 2; ++r)
#pragma unroll
        for (int j = 0; j < 2; ++j)
#pragma unroll
            for (int t = 0; t < 4; ++t) C[r][j][t] = 0.0f;
#pragma unroll 1
    for (int kc = kc0; kc < kc0 + kcn; ++kc) {
        uint4 ah0 = aHi[(kc * NRB + 0) * 32 + lane];
        uint4 ah1 = aHi[(kc * NRB + 1) * 32 + lane];
        uint4 bh = __ldg(bHi + (kc * NPT + npair0) * 32 + lane);
        mma_f16(C[0][0], ah0, bh.x, bh.y);
        mma_f16(C[1][0], ah1, bh.x, bh.y);
        mma_f16(C[0][1], ah0, bh.z, bh.w);
        mma_f16(C[1][1], ah1, bh.z, bh.w);
    }
}

// Partial K-slice, FIRST n-chunk only (O1: real N=2 lives in chunk 0).
__device__ __forceinline__ void mma_part1(const uint4* __restrict__ aHi,
                                          const uint4* __restrict__ bHi,
                                          int kc0, int kcn, float C[2][4]) {
    const int lane = threadIdx.x & 31;
#pragma unroll
    for (int r = 0; r < 2; ++r)
#pragma unroll
        for (int t = 0; t < 4; ++t) C[r][t] = 0.0f;
#pragma unroll 1
    for (int kc = kc0; kc < kc0 + kcn; ++kc) {
        uint4 ah0 = aHi[(kc * NRB + 0) * 32 + lane];
        uint4 ah1 = aHi[(kc * NRB + 1) * 32 + lane];
        uint4 bh = __ldg(bHi + kc * 32 + lane);   // NPT=1, npair0=0
        mma_f16(C[0], ah0, bh.x, bh.y);
        mma_f16(C[1], ah1, bh.x, bh.y);
    }
}

// Store a warp's narrow-layer partials to scratch (conflict-free float4 layout).
__device__ __forceinline__ void store_part(float4* scr4, int slice,
                                           float C[2][2][4]) {
    const int lane = threadIdx.x & 31;
#pragma unroll
    for (int r = 0; r < 2; ++r)
#pragma unroll
        for (int j = 0; j < 2; ++j) {
            int i = r * 2 + j;
            scr4[(i * 8 + slice) * 32 + lane] =
                make_float4(C[r][j][0], C[r][j][1], C[r][j][2], C[r][j][3]);
        }
}

// Reduce 4 k-slices (slices nh, nh+2, nh+4, nh+6) for n-half nh.
__device__ __forceinline__ void reduce4(const float4* scr4, int nh,
                                        float C[2][2][4]) {
    const int lane = threadIdx.x & 31;
#pragma unroll
    for (int i = 0; i < 4; ++i) {
        float4 a = scr4[(i * 8 + nh) * 32 + lane];
        float4 b = scr4[(i * 8 + 2 + nh) * 32 + lane];
        float4 c = scr4[(i * 8 + 4 + nh) * 32 + lane];
        float4 d = scr4[(i * 8 + 6 + nh) * 32 + lane];
        C[i >> 1][i & 1][0] = (a.x + b.x) + (c.x + d.x);
        C[i >> 1][i & 1][1] = (a.y + b.y) + (c.y + d.y);
        C[i >> 1][i & 1][2] = (a.z + b.z) + (c.z + d.z);
        C[i >> 1][i & 1][3] = (a.w + b.w) + (c.w + d.w);
    }
}

// Epilogue: bias(+ReLU), pack fp16 A fragments for the next layer.
template <int NC, bool RELU>
__device__ __forceinline__ void epi_region(float C[2][NC][4],
                                           const float* __restrict__ biasp,
                                           int nc0, uint32_t* dHi) {
    const int lane = threadIdx.x & 31;
    const int q = (lane & 3) * 2;
#pragma unroll
    for (int j = 0; j < NC; ++j) {
        int nc = nc0 + j;
        int kc = nc >> 1, odd = nc & 1;
        float b0 = __ldg(biasp + nc * 8 + q);
        float b1 = __ldg(biasp + nc * 8 + q + 1);
#pragma unroll
        for (int r = 0; r < 2; ++r) {
            float v0 = C[r][j][0] + b0, v1 = C[r][j][1] + b1;
            float v2 = C[r][j][2] + b0, v3 = C[r][j][3] + b1;
            if (RELU) {
                v0 = fmaxf(v0, 0.f); v1 = fmaxf(v1, 0.f);
                v2 = fmaxf(v2, 0.f); v3 = fmaxf(v3, 0.f);
            }
            int base = ((kc * NRB + r) * 32 + lane) * 4 + odd * 2;
            dHi[base] = pack_h2(v0, v1);
            dHi[base + 1] = pack_h2(v2, v3);
        }
    }
}

// ===========================================================================
// SMEM layout (bytes) — total 32256; 4 CTAs/SM
// ===========================================================================
#define SM_INPF  0          // fp32 [32][49] = 6272 (reused as routs [32][33])
#define SM_SHI   6272       // inp frags: 3*2*512 = 3072
#define SM_PHI   9344       // pred frags: 2*2*512 = 2048
#define SM_AHI   11392      // act frags: 16*2*512 = 16384 (doubles as scratch)
#define SM_OFFS  27776      // fp32 [32][2] = 256
#define SM_OUT   28032      // fp32 [32][33] = 4224
#define SMEM_BYTES 32256

// ===========================================================================
// Fused kernel: 32 queries per CTA, 8 warps, 4 CTAs/SM.
// Wide layers: warp = unique 32 N-cols. Narrow layers: k-split over all warps.
// ===========================================================================
__global__ __launch_bounds__(256, 4) void fused_kernel(
    const float* __restrict__ b0p, const float* __restrict__ b1p,
    const float* __restrict__ b2p, const float* __restrict__ rb0p,
    const float* __restrict__ rb1p, const float* __restrict__ ob0p,
    const float* __restrict__ ob1p, float* __restrict__ out) {
    extern __shared__ __align__(16) unsigned char smraw[];
    float* inpF = reinterpret_cast<float*>(smraw + SM_INPF);
    uint4* SHi = reinterpret_cast<uint4*>(smraw + SM_SHI);
    uint4* PHi = reinterpret_cast<uint4*>(smraw + SM_PHI);
    uint4* AHi = reinterpret_cast<uint4*>(smraw + SM_AHI);
    uint32_t* PHiW = reinterpret_cast<uint32_t*>(PHi);
    uint32_t* AHiW = reinterpret_cast<uint32_t*>(AHi);
    float4* scr4 = reinterpret_cast<float4*>(smraw + SM_AHI);  // narrow-layer scratch
    float* offs  = reinterpret_cast<float*>(smraw + SM_OFFS);
    float* outst = reinterpret_cast<float*>(smraw + SM_OUT);
    float* routs = inpF;   // reuse after L1 staging

    const int tid = threadIdx.x;
    const int lane = tid & 31;
    const int wid = tid >> 5;

    const int q0 = blockIdx.x * MT;
    const int b = q0 >> 16;
    const int qbase = q0 & (QPB - 1);
    const float* xb = g_xt + b * (Hn * Wn * Cn);

    const uint4* WL1 = (const uint4*)(g_wimg + WOFF_L1);
    const uint4* WL2 = (const uint4*)(g_wimg + WOFF_L2);
    const uint4* WL3 = (const uint4*)(g_wimg + WOFF_L3);
    const uint4* WR0 = (const uint4*)(g_wimg + WOFF_R0);
    const uint4* WR1 = (const uint4*)(g_wimg + WOFF_R1);
    const uint4* WO0 = (const uint4*)(g_wimg + WOFF_O0);
    const uint4* WO1 = (const uint4*)(g_wimg + WOFF_O1);

    // ---- Stage A: sampling -> inpF [32][49] --------------------------------
#pragma unroll 1
    for (int i = 0; i < 4; ++i) {
        int m = wid * 4 + i;
        int ql = qbase + m;
        int oy = ql >> 8, ox = ql & 255;
        float gy = (2.0f * oy + 1.0f) * (1.0f / 256.0f) - 1.0f;
        float gx = (2.0f * ox + 1.0f) * (1.0f / 256.0f) - 1.0f;
        int ix0, iy0;
        float wx[4], wy[4];
        prep_axis(gx, ix0, wx);
        prep_axis(gy, iy0, wy);
        inpF[m * 49 + lane] = sample_c(xb, lane, ix0, iy0, wx, wy);
        if (lane == 0) {
            float syw = 0.f, sy = 0.f, sxw = 0.f, sx = 0.f;
#pragma unroll
            for (int ii = 0; ii < 4; ++ii) {
                int yi = iy0 - 1 + ii;
                if ((unsigned)yi < 128u) {
                    float yco = (2.0f * yi + 1.0f) * (1.0f / 128.0f) - 1.0f;
                    syw += wy[ii]; sy = fmaf(wy[ii], yco, sy);
                }
            }
#pragma unroll
            for (int jj = 0; jj < 4; ++jj) {
                int xj = ix0 - 1 + jj;
                if ((unsigned)xj < 128u) {
                    float xco = (2.0f * xj + 1.0f) * (1.0f / 128.0f) - 1.0f;
                    sxw += wx[jj]; sx = fmaf(wx[jj], xco, sx);
                }
            }
            inpF[m * 49 + 32] = (gy - sy * sxw) * 128.0f;
            inpF[m * 49 + 33] = (gx - sx * syw) * 128.0f;
            float rc = (ql < 2) ? 1.0f : 128.0f;   // faithful cell quirk
            inpF[m * 49 + 34] = rc;
            inpF[m * 49 + 35] = rc;
        }
        if (lane >= 4 && lane < 16) inpF[m * 49 + 32 + lane] = 0.0f;  // pad 36..47
    }
    __syncthreads();

    // ---- Stage S frags: inpF -> S (A-fragment fp16, K=48) -------------------
    if (wid < 6) {
        int kc = wid >> 1, rbs = wid & 1;
        int r0 = rbs * 16 + (lane >> 2);
        int k0 = kc * 16 + (lane & 3) * 2;
        uint4 hi;
        hi.x = pack_h2(inpF[r0 * 49 + k0], inpF[r0 * 49 + k0 + 1]);
        hi.y = pack_h2(inpF[(r0 + 8) * 49 + k0], inpF[(r0 + 8) * 49 + k0 + 1]);
        hi.z = pack_h2(inpF[r0 * 49 + k0 + 8], inpF[r0 * 49 + k0 + 9]);
        hi.w = pack_h2(inpF[(r0 + 8) * 49 + k0 + 8], inpF[(r0 + 8) * 49 + k0 + 9]);
        SHi[(kc * NRB + rbs) * 32 + lane] = hi;
    }
    __syncthreads();

    float C4[2][4][4];
    float C2[2][2][4];

    // ---- L1: S(K=48) x W0 -> h1 (N=256) -> A --------------------------------
    mma_layer<3, 4, 16>(SHi, WL1, wid * 4, C4);
    epi_region<4, true>(C4, b0p, wid * 4, AHiW);
    __syncthreads();

    // ---- L2: A(K=256) x W1 -> h2 (N=256) -> A (in place) --------------------
    mma_layer<16, 4, 16>(AHi, WL2, wid * 4, C4);
    __syncthreads();
    epi_region<4, true>(C4, b1p, wid * 4, AHiW);
    __syncthreads();

    // ---- L3 (k-split): A(K=256) x W2 -> pred (N=32) -> P --------------------
    mma_part(AHi, WL3, wid & 1, (wid >> 1) * 4, 4, 2, C2);
    __syncthreads();                     // all reads of A done
    store_part(scr4, wid, C2);
    __syncthreads();
    if (wid < 2) {
        reduce4(scr4, wid, C2);
        epi_region<2, false>(C2, b2p, wid * 2, PHiW);
    }
    __syncthreads();

    // ---- O0: P(K=32) x OW0 -> off-hidden (N=256) -> A ------------------------
    mma_layer<2, 4, 16>(PHi, WO0, wid * 4, C4);
    epi_region<4, true>(C4, ob0p, wid * 4, AHiW);
    __syncthreads();

    // ---- O1 (k-split, chunk 0 only): A(K=256) x OW1 -> offsets; R0 overlaps --
    float C2b[2][4];
    mma_part1(AHi, WO1, wid * 2, 2, C2b);
    __syncthreads();                     // all reads of A done
    {   // store only i = r*2 rows (chunk j=0) — matches reduction below
#pragma unroll
        for (int r = 0; r < 2; ++r)
            scr4[((r * 2) * 8 + wid) * 32 + lane] =
                make_float4(C2b[r][0], C2b[r][1], C2b[r][2], C2b[r][3]);
    }
    __syncthreads();
    if (wid == 0) {
        float o[2][4];
#pragma unroll
        for (int ri = 0; ri < 2; ++ri) {
            int i = ri * 2;
            float4 acc = scr4[(i * 8 + 0) * 32 + lane];
#pragma unroll
            for (int s = 1; s < 8; ++s) {
                float4 v = scr4[(i * 8 + s) * 32 + lane];
                acc.x += v.x; acc.y += v.y; acc.z += v.z; acc.w += v.w;
            }
            o[ri][0] = acc.x; o[ri][1] = acc.y; o[ri][2] = acc.z; o[ri][3] = acc.w;
        }
        if ((lane & 3) == 0) {
            float o0 = __ldg(ob1p + 0), o1 = __ldg(ob1p + 1);
#pragma unroll
            for (int r = 0; r < 2; ++r) {
                int row = r * 16 + (lane >> 2);
                offs[row * 2 + 0] = o[r][0] + o0;
                offs[row * 2 + 1] = o[r][1] + o1;
                offs[(row + 8) * 2 + 0] = o[r][2] + o0;
                offs[(row + 8) * 2 + 1] = o[r][3] + o1;
            }
        }
    }
    // R0 mma overlaps with warp 0's reduction (reads only P-fragments)
    mma_layer<2, 4, 16>(PHi, WR0, wid * 4, C4);
    __syncthreads();                     // offs written; scratch consumed
    epi_region<4, true>(C4, rb0p, wid * 4, AHiW);
    __syncthreads();

    // ---- R1 (k-split): A(K=256) x RW1 -> routing (N=32) -> routs fp32 --------
    mma_part(AHi, WR1, wid & 1, (wid >> 1) * 4, 4, 2, C2);
    __syncthreads();                     // all reads of A done
    store_part(scr4, wid, C2);
    __syncthreads();
    if (wid < 2) {
        reduce4(scr4, wid, C2);
        const int q = (lane & 3) * 2;
#pragma unroll
        for (int j = 0; j < 2; ++j) {
            int nc = wid * 2 + j;
            float bb0 = __ldg(rb1p + nc * 8 + q);
            float bb1 = __ldg(rb1p + nc * 8 + q + 1);
#pragma unroll
            for (int r = 0; r < 2; ++r) {
                int row = r * 16 + (lane >> 2);
                routs[row * 33 + nc * 8 + q]     = C2[r][j][0] + bb0;
                routs[row * 33 + nc * 8 + q + 1] = C2[r][j][1] + bb1;
                routs[(row + 8) * 33 + nc * 8 + q]     = C2[r][j][2] + bb0;
                routs[(row + 8) * 33 + nc * 8 + q + 1] = C2[r][j][3] + bb1;
            }
        }
    }
    __syncthreads();

    // ---- Stage C: offset resample + modulate ---------------------------------
#pragma unroll 1
    for (int i = 0; i < 4; ++i) {
        int m = wid * 4 + i;
        int ql = qbase + m;
        int oy = ql >> 8, ox = ql & 255;
        float gy = (2.0f * oy + 1.0f) * (1.0f / 256.0f) - 1.0f;
        float gx = (2.0f * ox + 1.0f) * (1.0f / 256.0f) - 1.0f;
        float gx2 = gx + offs[m * 2 + 0];
        float gy2 = gy + offs[m * 2 + 1];
        int ix0, iy0;
        float wx[4], wy[4];
        prep_axis(gx2, ix0, wx);
        prep_axis(gy2, iy0, wy);
        float v = sample_c(xb, lane, ix0, iy0, wx, wy);
        outst[lane * 33 + m] = v * (1.0f + routs[m * 33 + lane]);
    }
    __syncthreads();

    // ---- writeout -------------------------------------------------------------
    {
        int c = tid >> 3;
        int part = tid & 7;
        const float* src = outst + c * 33 + part * 4;
        float* dst = out + ((size_t)(b * Cn + c)) * QPB + qbase + part * 4;
        *reinterpret_cast<float4*>(dst) =
            make_float4(src[0], src[1], src[2], src[3]);
    }
}

// ===========================================================================
// kernel_launch — 2 launches: setup (xt + prep), fused
// ===========================================================================
extern "C" void kernel_launch(void* const* d_in, const int* in_sizes, int n_in,
                              void* d_out, int out_size) {
    const float* x   = (const float*)d_in[0];
    const float* w0  = (const float*)d_in[1];
    const float* b0  = (const float*)d_in[2];
    const float* w1  = (const float*)d_in[3];
    const float* b1  = (const float*)d_in[4];
    const float* w2  = (const float*)d_in[5];
    const float* b2  = (const float*)d_in[6];
    const float* rw0 = (const float*)d_in[7];
    const float* rb0 = (const float*)d_in[8];
    const float* rw1 = (const float*)d_in[9];
    const float* rb1 = (const float*)d_in[10];
    const float* ow0 = (const float*)d_in[11];
    const float* ob0 = (const float*)d_in[12];
    const float* ow1 = (const float*)d_in[13];
    const float* ob1 = (const float*)d_in[14];
    float* out = (float*)d_out;

    setup_kernel<<<dim3(512, 8), 256>>>(x, w0, w1, w2, rw0, rw1, ow0, ow1);

    cudaFuncSetAttribute(fused_kernel,
                         cudaFuncAttributeMaxDynamicSharedMemorySize, SMEM_BYTES);
    fused_kernel<<<NCTA, 256, SMEM_BYTES>>>(b0, b1, b2, rb0, rb1, ob0, ob1, out);
}

// round 15
// speedup vs baseline: 1.4945x; 1.0878x over previous
#include <cuda_runtime.h>
#include <cuda_fp16.h>
#include <cstdint>

// ===========================================================================
// Problem constants (fixed: B=4, C=32, H=W=128, scale=2)
// ===========================================================================
#define Bn    4
#define Cn    32
#define Hn    128
#define Wn    128
#define QPB   65536
#define NQ    (Bn * QPB)
#define MT    32                   // queries per CTA
#define NCTA  (NQ / MT)            // 8192
#define NRB   2                    // row-blocks (16 rows) per CTA

// ===========================================================================
// Global scratch
// ===========================================================================
__device__ float g_xt[Bn * Hn * Wn * Cn];   // channels-last x

// Weight images: B-fragment-packed fp16.
#define WOFF_L1  0u          // KC=3,  NPT=16 -> 24576
#define WOFF_L2  24576u      // KC=16, NPT=16 -> 131072
#define WOFF_L3  155648u     // KC=16, NPT=2  -> 16384
#define WOFF_R0  172032u     // KC=2,  NPT=16 -> 16384
#define WOFF_R1  188416u     // KC=16, NPT=2  -> 16384
#define WOFF_O0  204800u     // KC=2,  NPT=16 -> 16384
#define WOFF_O1  221184u     // KC=16, NPT=1  -> 8192
#define WIMG_TOTAL 229376u
__device__ __align__(16) unsigned char g_wimg[WIMG_TOTAL];

// ===========================================================================
// Setup kernel: y==0 -> transpose x; y>=1 -> weight prep for layer y-1.
// ===========================================================================
__global__ void setup_kernel(const float* __restrict__ x,
                             const float* __restrict__ w0, const float* __restrict__ w1,
                             const float* __restrict__ w2, const float* __restrict__ rw0,
                             const float* __restrict__ rw1, const float* __restrict__ ow0,
                             const float* __restrict__ ow1) {
    const int tid = threadIdx.x;
    if (blockIdx.y == 0) {
        __shared__ float s[Cn][Wn + 1];
        const int by = blockIdx.x;      // 0..511
#pragma unroll
        for (int it = 0; it < 16; ++it) {
            int idx = tid + it * 256;
            int c = idx >> 7, xc = idx & 127;
            int b = by >> 7, y = by & 127;
            s[c][xc] = x[((b * Cn + c) * Hn + y) * Wn + xc];
        }
        __syncthreads();
#pragma unroll
        for (int it = 0; it < 16; ++it) {
            int idx = tid + it * 256;
            int xc = idx >> 5, c = idx & 31;
            g_xt[(by * Wn + xc) * Cn + c] = s[c][xc];
        }
        return;
    }
    const float* W;
    int Kdim, Ndim, Kt, Nt;
    uint32_t dstOff;
    switch (blockIdx.y - 1) {
        case 0: W = w0;  Kdim = 36;  Ndim = 256; Kt = 48;  Nt = 256; dstOff = WOFF_L1; break;
        case 1: W = w1;  Kdim = 256; Ndim = 256; Kt = 256; Nt = 256; dstOff = WOFF_L2; break;
        case 2: W = w2;  Kdim = 256; Ndim = 32;  Kt = 256; Nt = 32;  dstOff = WOFF_L3; break;
        case 3: W = rw0; Kdim = 32;  Ndim = 256; Kt = 32;  Nt = 256; dstOff = WOFF_R0; break;
        case 4: W = rw1; Kdim = 256; Ndim = 32;  Kt = 256; Nt = 32;  dstOff = WOFF_R1; break;
        case 5: W = ow0; Kdim = 32;  Ndim = 256; Kt = 32;  Nt = 256; dstOff = WOFF_O0; break;
        default: W = ow1; Kdim = 256; Ndim = 2;  Kt = 256; Nt = 16;  dstOff = WOFF_O1; break;
    }
    int idx = blockIdx.x * 256 + tid;
    if (idx >= Kt * Nt) return;
    int k = idx / Nt;
    int n = idx % Nt;
    float w = (k < Kdim && n < Ndim) ? W[k * Ndim + n] : 0.0f;
    __half hb = __float2half_rn(w);
    int kc = k >> 4, ki = k & 15;
    int nc = n >> 3, ni = n & 7;
    int npair = nc >> 1;
    int lane = ni * 4 + ((ki & 7) >> 1);
    int word = (ki >> 3) + (nc & 1) * 2;
    int half = ki & 1;
    uint32_t off = (uint32_t)(((kc * (Nt >> 4) + npair) * 32 + lane) * 16 +
                              word * 4 + half * 2);
    *reinterpret_cast<unsigned short*>(g_wimg + dstOff + off) = __half_as_ushort(hb);
}

// ===========================================================================
// Bicubic helpers (torch aten, A=-0.75)
// ===========================================================================
__device__ __forceinline__ void prep_axis(float g, int& i0, float w[4]) {
    float p = ((g + 1.0f) * 128.0f - 1.0f) * 0.5f;
    float fp = floorf(p);
    i0 = (int)fp;
    float t = p - fp;
    const float A = -0.75f;
    float xx = t + 1.0f;
    w[0] = ((A * xx - 5.0f * A) * xx + 8.0f * A) * xx - 4.0f * A;
    w[1] = ((A + 2.0f) * t - (A + 3.0f)) * t * t + 1.0f;
    float s = 1.0f - t;
    w[2] = ((A + 2.0f) * s - (A + 3.0f)) * s * s + 1.0f;
    w[3] = 1.0f - w[0] - w[1] - w[2];
}

// guarded (boundary) path
__device__ __forceinline__ float sample_slow(const float* __restrict__ xb, int lane,
                                             int ix0, int iy0,
                                             const float* wx, const float* wy) {
    float acc = 0.0f;
#pragma unroll
    for (int i = 0; i < 4; ++i) {
        int yi = iy0 - 1 + i;
        if ((unsigned)yi < 128u) {
            const float* rp = xb + yi * (Wn * Cn) + lane;
            float r = 0.0f;
#pragma unroll
            for (int j = 0; j < 4; ++j) {
                int xj = ix0 - 1 + j;
                if ((unsigned)xj < 128u) r = fmaf(wx[j], __ldg(rp + xj * Cn), r);
            }
            acc = fmaf(wy[i], r, acc);
        }
    }
    return acc;
}

// unguarded interior path (ix0 in [1,125], iy0 in [1,125]); warp-uniform branch
__device__ __forceinline__ float sample_c(const float* __restrict__ xb, int lane,
                                          int ix0, int iy0,
                                          const float* wx, const float* wy) {
    if ((unsigned)(ix0 - 1) <= 124u && (unsigned)(iy0 - 1) <= 124u) {
        const float* rp = xb + (iy0 - 1) * (Wn * Cn) + (ix0 - 1) * Cn + lane;
        float acc = 0.0f;
#pragma unroll
        for (int i = 0; i < 4; ++i) {
            float r = wx[0] * __ldg(rp);
            r = fmaf(wx[1], __ldg(rp + Cn), r);
            r = fmaf(wx[2], __ldg(rp + 2 * Cn), r);
            r = fmaf(wx[3], __ldg(rp + 3 * Cn), r);
            acc = fmaf(wy[i], r, acc);
            rp += Wn * Cn;
        }
        return acc;
    }
    return sample_slow(xb, lane, ix0, iy0, wx, wy);
}

// packed fp16x2 (v1 in high half, v0 in low half)
__device__ __forceinline__ uint32_t pack_h2(float v0, float v1) {
    __half2 h = __floats2half2_rn(v0, v1);
    return *reinterpret_cast<uint32_t*>(&h);
}

// ===========================================================================
// mma.sync m16n8k16 fp16
// ===========================================================================
__device__ __forceinline__ void mma_f16(float* c, const uint4& a,
                                        uint32_t b0, uint32_t b1) {
    asm("mma.sync.aligned.m16n8k16.row.col.f32.f16.f16.f32 "
        "{%0,%1,%2,%3},{%4,%5,%6,%7},{%8,%9},{%0,%1,%2,%3};"
        : "+f"(c[0]), "+f"(c[1]), "+f"(c[2]), "+f"(c[3])
        : "r"(a.x), "r"(a.y), "r"(a.z), "r"(a.w), "r"(b0), "r"(b1));
}

// Wide K-loop over BOTH 16-row blocks, single-term: C += A*B.
template <int KC, int NC, int NPT>
__device__ __forceinline__ void mma_layer(const uint4* __restrict__ aHi,
                                          const uint4* __restrict__ bHi,
                                          int nc0, float C[2][NC][4]) {
    const int lane = threadIdx.x & 31;
#pragma unroll
    for (int r = 0; r < 2; ++r)
#pragma unroll
        for (int j = 0; j < NC; ++j)
#pragma unroll
            for (int t = 0; t < 4; ++t) C[r][j][t] = 0.0f;
    const int npair0 = nc0 >> 1;
#pragma unroll 4
    for (int kc = 0; kc < KC; ++kc) {
        uint4 ah0 = aHi[(kc * NRB + 0) * 32 + lane];
        uint4 ah1 = aHi[(kc * NRB + 1) * 32 + lane];
#pragma unroll
        for (int p = 0; p < NC / 2; ++p) {
            uint4 bh = __ldg(bHi + (kc * NPT + npair0 + p) * 32 + lane);
            mma_f16(C[0][2 * p], ah0, bh.x, bh.y);
            mma_f16(C[1][2 * p], ah1, bh.x, bh.y);
            mma_f16(C[0][2 * p + 1], ah0, bh.z, bh.w);
            mma_f16(C[1][2 * p + 1], ah1, bh.z, bh.w);
        }
    }
}

// Partial K-slice for narrow (N<=32) layers: one npair, kc in [kc0, kc0+kcn).
__device__ __forceinline__ void mma_part(const uint4* __restrict__ aHi,
                                         const uint4* __restrict__ bHi,
                                         int npair0, int kc0, int kcn, int NPT,
                                         float C[2][2][4]) {
    const int lane = threadIdx.x & 31;
#pragma unroll
    for (int r = 0; r < 2; ++r)
#pragma unroll
        for (int j = 0; j < 2; ++j)
#pragma unroll
            for (int t = 0; t < 4; ++t) C[r][j][t] = 0.0f;
#pragma unroll 4
    for (int kc = kc0; kc < kc0 + kcn; ++kc) {
        uint4 ah0 = aHi[(kc * NRB + 0) * 32 + lane];
        uint4 ah1 = aHi[(kc * NRB + 1) * 32 + lane];
        uint4 bh = __ldg(bHi + (kc * NPT + npair0) * 32 + lane);
        mma_f16(C[0][0], ah0, bh.x, bh.y);
        mma_f16(C[1][0], ah1, bh.x, bh.y);
        mma_f16(C[0][1], ah0, bh.z, bh.w);
        mma_f16(C[1][1], ah1, bh.z, bh.w);
    }
}

// Partial K-slice, FIRST n-chunk only (O1: real N=2 lives in chunk 0).
__device__ __forceinline__ void mma_part1(const uint4* __restrict__ aHi,
                                          const uint4* __restrict__ bHi,
                                          int kc0, int kcn, float C[2][4]) {
    const int lane = threadIdx.x & 31;
#pragma unroll
    for (int r = 0; r < 2; ++r)
#pragma unroll
        for (int t = 0; t < 4; ++t) C[r][t] = 0.0f;
#pragma unroll 2
    for (int kc = kc0; kc < kc0 + kcn; ++kc) {
        uint4 ah0 = aHi[(kc * NRB + 0) * 32 + lane];
        uint4 ah1 = aHi[(kc * NRB + 1) * 32 + lane];
        uint4 bh = __ldg(bHi + kc * 32 + lane);   // NPT=1, npair0=0
        mma_f16(C[0], ah0, bh.x, bh.y);
        mma_f16(C[1], ah1, bh.x, bh.y);
    }
}

// Store a warp's narrow-layer partials to scratch (conflict-free float4 layout).
__device__ __forceinline__ void store_part(float4* scr4, int slice,
                                           float C[2][2][4]) {
    const int lane = threadIdx.x & 31;
#pragma unroll
    for (int r = 0; r < 2; ++r)
#pragma unroll
        for (int j = 0; j < 2; ++j) {
            int i = r * 2 + j;
            scr4[(i * 8 + slice) * 32 + lane] =
                make_float4(C[r][j][0], C[r][j][1], C[r][j][2], C[r][j][3]);
        }
}

// Reduce 4 k-slices (slices nh, nh+2, nh+4, nh+6) for n-half nh.
__device__ __forceinline__ void reduce4(const float4* scr4, int nh,
                                        float C[2][2][4]) {
    const int lane = threadIdx.x & 31;
#pragma unroll
    for (int i = 0; i < 4; ++i) {
        float4 a = scr4[(i * 8 + nh) * 32 + lane];
        float4 b = scr4[(i * 8 + 2 + nh) * 32 + lane];
        float4 c = scr4[(i * 8 + 4 + nh) * 32 + lane];
        float4 d = scr4[(i * 8 + 6 + nh) * 32 + lane];
        C[i >> 1][i & 1][0] = (a.x + b.x) + (c.x + d.x);
        C[i >> 1][i & 1][1] = (a.y + b.y) + (c.y + d.y);
        C[i >> 1][i & 1][2] = (a.z + b.z) + (c.z + d.z);
        C[i >> 1][i & 1][3] = (a.w + b.w) + (c.w + d.w);
    }
}

// Epilogue: bias(+ReLU), pack fp16 A fragments for the next layer.
template <int NC, bool RELU>
__device__ __forceinline__ void epi_region(float C[2][NC][4],
                                           const float* __restrict__ biasp,
                                           int nc0, uint32_t* dHi) {
    const int lane = threadIdx.x & 31;
    const int q = (lane & 3) * 2;
#pragma unroll
    for (int j = 0; j < NC; ++j) {
        int nc = nc0 + j;
        int kc = nc >> 1, odd = nc & 1;
        float b0 = __ldg(biasp + nc * 8 + q);
        float b1 = __ldg(biasp + nc * 8 + q + 1);
#pragma unroll
        for (int r = 0; r < 2; ++r) {
            float v0 = C[r][j][0] + b0, v1 = C[r][j][1] + b1;
            float v2 = C[r][j][2] + b0, v3 = C[r][j][3] + b1;
            if (RELU) {
                v0 = fmaxf(v0, 0.f); v1 = fmaxf(v1, 0.f);
                v2 = fmaxf(v2, 0.f); v3 = fmaxf(v3, 0.f);
            }
            int base = ((kc * NRB + r) * 32 + lane) * 4 + odd * 2;
            dHi[base] = pack_h2(v0, v1);
            dHi[base + 1] = pack_h2(v2, v3);
        }
    }
}

// ===========================================================================
// SMEM layout (bytes) — total 32256; 4 CTAs/SM
// ===========================================================================
#define SM_INPF  0          // fp32 [32][49] = 6272 (reused as routs [32][33])
#define SM_SHI   6272       // inp frags: 3*2*512 = 3072
#define SM_PHI   9344       // pred frags: 2*2*512 = 2048
#define SM_AHI   11392      // act frags: 16*2*512 = 16384 (doubles as scratch)
#define SM_OFFS  27776      // fp32 [32][2] = 256
#define SM_OUT   28032      // fp32 [32][33] = 4224
#define SMEM_BYTES 32256

// ===========================================================================
// Fused kernel: 32 queries per CTA, 8 warps, 4 CTAs/SM.
// Wide layers: warp = unique 32 N-cols. Narrow layers: k-split over all warps.
// ===========================================================================
__global__ __launch_bounds__(256, 4) void fused_kernel(
    const float* __restrict__ b0p, const float* __restrict__ b1p,
    const float* __restrict__ b2p, const float* __restrict__ rb0p,
    const float* __restrict__ rb1p, const float* __restrict__ ob0p,
    const float* __restrict__ ob1p, float* __restrict__ out) {
    extern __shared__ __align__(16) unsigned char smraw[];
    float* inpF = reinterpret_cast<float*>(smraw + SM_INPF);
    uint4* SHi = reinterpret_cast<uint4*>(smraw + SM_SHI);
    uint4* PHi = reinterpret_cast<uint4*>(smraw + SM_PHI);
    uint4* AHi = reinterpret_cast<uint4*>(smraw + SM_AHI);
    uint32_t* PHiW = reinterpret_cast<uint32_t*>(PHi);
    uint32_t* AHiW = reinterpret_cast<uint32_t*>(AHi);
    float4* scr4 = reinterpret_cast<float4*>(smraw + SM_AHI);  // narrow-layer scratch
    float* offs  = reinterpret_cast<float*>(smraw + SM_OFFS);
    float* outst = reinterpret_cast<float*>(smraw + SM_OUT);
    float* routs = inpF;   // reuse after L1 staging

    const int tid = threadIdx.x;
    const int lane = tid & 31;
    const int wid = tid >> 5;

    const int q0 = blockIdx.x * MT;
    const int b = q0 >> 16;
    const int qbase = q0 & (QPB - 1);
    const float* xb = g_xt + b * (Hn * Wn * Cn);

    const uint4* WL1 = (const uint4*)(g_wimg + WOFF_L1);
    const uint4* WL2 = (const uint4*)(g_wimg + WOFF_L2);
    const uint4* WL3 = (const uint4*)(g_wimg + WOFF_L3);
    const uint4* WR0 = (const uint4*)(g_wimg + WOFF_R0);
    const uint4* WR1 = (const uint4*)(g_wimg + WOFF_R1);
    const uint4* WO0 = (const uint4*)(g_wimg + WOFF_O0);
    const uint4* WO1 = (const uint4*)(g_wimg + WOFF_O1);

    // ---- Stage A: sampling -> inpF [32][49] --------------------------------
    // All 32 queries of this CTA live in ONE output row: y-work is CTA-uniform.
    {
        const int oy = qbase >> 8;
        float gy = (2.0f * oy + 1.0f) * (1.0f / 256.0f) - 1.0f;
        int iy0;
        float wy[4];
        prep_axis(gy, iy0, wy);
        // uniform y-side rel-coord terms
        float syw = 0.f, sy = 0.f;
#pragma unroll
        for (int ii = 0; ii < 4; ++ii) {
            int yi = iy0 - 1 + ii;
            if ((unsigned)yi < 128u) {
                float yco = (2.0f * yi + 1.0f) * (1.0f / 128.0f) - 1.0f;
                syw += wy[ii]; sy = fmaf(wy[ii], yco, sy);
            }
        }
#pragma unroll 2
        for (int i = 0; i < 4; ++i) {
            int m = wid * 4 + i;
            int ox = (qbase + m) & 255;
            float gx = (2.0f * ox + 1.0f) * (1.0f / 256.0f) - 1.0f;
            int ix0;
            float wx[4];
            prep_axis(gx, ix0, wx);
            inpF[m * 49 + lane] = sample_c(xb, lane, ix0, iy0, wx, wy);
            if (lane == 0) {
                float sxw = 0.f, sx = 0.f;
#pragma unroll
                for (int jj = 0; jj < 4; ++jj) {
                    int xj = ix0 - 1 + jj;
                    if ((unsigned)xj < 128u) {
                        float xco = (2.0f * xj + 1.0f) * (1.0f / 128.0f) - 1.0f;
                        sxw += wx[jj]; sx = fmaf(wx[jj], xco, sx);
                    }
                }
                inpF[m * 49 + 32] = (gy - sy * sxw) * 128.0f;
                inpF[m * 49 + 33] = (gx - sx * syw) * 128.0f;
                int ql = qbase + m;
                float rc = (ql < 2) ? 1.0f : 128.0f;   // faithful cell quirk
                inpF[m * 49 + 34] = rc;
                inpF[m * 49 + 35] = rc;
            }
            if (lane >= 4 && lane < 16) inpF[m * 49 + 32 + lane] = 0.0f;  // pad
        }
    }
    __syncthreads();

    // ---- Stage S frags: inpF -> S (A-fragment fp16, K=48) -------------------
    if (wid < 6) {
        int kc = wid >> 1, rbs = wid & 1;
        int r0 = rbs * 16 + (lane >> 2);
        int k0 = kc * 16 + (lane & 3) * 2;
        uint4 hi;
        hi.x = pack_h2(inpF[r0 * 49 + k0], inpF[r0 * 49 + k0 + 1]);
        hi.y = pack_h2(inpF[(r0 + 8) * 49 + k0], inpF[(r0 + 8) * 49 + k0 + 1]);
        hi.z = pack_h2(inpF[r0 * 49 + k0 + 8], inpF[r0 * 49 + k0 + 9]);
        hi.w = pack_h2(inpF[(r0 + 8) * 49 + k0 + 8], inpF[(r0 + 8) * 49 + k0 + 9]);
        SHi[(kc * NRB + rbs) * 32 + lane] = hi;
    }
    __syncthreads();

    float C4[2][4][4];
    float C2[2][2][4];

    // ---- L1: S(K=48) x W0 -> h1 (N=256) -> A --------------------------------
    mma_layer<3, 4, 16>(SHi, WL1, wid * 4, C4);
    epi_region<4, true>(C4, b0p, wid * 4, AHiW);
    __syncthreads();

    // ---- L2: A(K=256) x W1 -> h2 (N=256) -> A (in place) --------------------
    mma_layer<16, 4, 16>(AHi, WL2, wid * 4, C4);
    __syncthreads();
    epi_region<4, true>(C4, b1p, wid * 4, AHiW);
    __syncthreads();

    // ---- L3 (k-split): A(K=256) x W2 -> pred (N=32) -> P --------------------
    mma_part(AHi, WL3, wid & 1, (wid >> 1) * 4, 4, 2, C2);
    __syncthreads();                     // all reads of A done
    store_part(scr4, wid, C2);
    __syncthreads();
    if (wid < 2) {
        reduce4(scr4, wid, C2);
        epi_region<2, false>(C2, b2p, wid * 2, PHiW);
    }
    __syncthreads();

    // ---- O0: P(K=32) x OW0 -> off-hidden (N=256) -> A ------------------------
    mma_layer<2, 4, 16>(PHi, WO0, wid * 4, C4);
    epi_region<4, true>(C4, ob0p, wid * 4, AHiW);
    __syncthreads();

    // ---- O1 (k-split, chunk 0 only): A(K=256) x OW1 -> offsets; R0 overlaps --
    float C2b[2][4];
    mma_part1(AHi, WO1, wid * 2, 2, C2b);
    __syncthreads();                     // all reads of A done
    {   // store only i = r*2 rows (chunk j=0) — matches reduction below
#pragma unroll
        for (int r = 0; r < 2; ++r)
            scr4[((r * 2) * 8 + wid) * 32 + lane] =
                make_float4(C2b[r][0], C2b[r][1], C2b[r][2], C2b[r][3]);
    }
    __syncthreads();
    if (wid == 0) {
        float o[2][4];
#pragma unroll
        for (int ri = 0; ri < 2; ++ri) {
            int i = ri * 2;
            float4 acc = scr4[(i * 8 + 0) * 32 + lane];
#pragma unroll
            for (int s = 1; s < 8; ++s) {
                float4 v = scr4[(i * 8 + s) * 32 + lane];
                acc.x += v.x; acc.y += v.y; acc.z += v.z; acc.w += v.w;
            }
            o[ri][0] = acc.x; o[ri][1] = acc.y; o[ri][2] = acc.z; o[ri][3] = acc.w;
        }
        if ((lane & 3) == 0) {
            float o0 = __ldg(ob1p + 0), o1 = __ldg(ob1p + 1);
#pragma unroll
            for (int r = 0; r < 2; ++r) {
                int row = r * 16 + (lane >> 2);
                offs[row * 2 + 0] = o[r][0] + o0;
                offs[row * 2 + 1] = o[r][1] + o1;
                offs[(row + 8) * 2 + 0] = o[r][2] + o0;
                offs[(row + 8) * 2 + 1] = o[r][3] + o1;
            }
        }
    }
    // R0 mma overlaps with warp 0's reduction (reads only P-fragments)
    mma_layer<2, 4, 16>(PHi, WR0, wid * 4, C4);
    __syncthreads();                     // offs written; scratch consumed
    epi_region<4, true>(C4, rb0p, wid * 4, AHiW);
    __syncthreads();

    // ---- R1 (k-split): A(K=256) x RW1 -> routing (N=32) -> routs fp32 --------
    mma_part(AHi, WR1, wid & 1, (wid >> 1) * 4, 4, 2, C2);
    __syncthreads();                     // all reads of A done
    store_part(scr4, wid, C2);
    __syncthreads();
    if (wid < 2) {
        reduce4(scr4, wid, C2);
        const int q = (lane & 3) * 2;
#pragma unroll
        for (int j = 0; j < 2; ++j) {
            int nc = wid * 2 + j;
            float bb0 = __ldg(rb1p + nc * 8 + q);
            float bb1 = __ldg(rb1p + nc * 8 + q + 1);
#pragma unroll
            for (int r = 0; r < 2; ++r) {
                int row = r * 16 + (lane >> 2);
                routs[row * 33 + nc * 8 + q]     = C2[r][j][0] + bb0;
                routs[row * 33 + nc * 8 + q + 1] = C2[r][j][1] + bb1;
                routs[(row + 8) * 33 + nc * 8 + q]     = C2[r][j][2] + bb0;
                routs[(row + 8) * 33 + nc * 8 + q + 1] = C2[r][j][3] + bb1;
            }
        }
    }
    __syncthreads();

    // ---- Stage C: offset resample + modulate ---------------------------------
#pragma unroll 2
    for (int i = 0; i < 4; ++i) {
        int m = wid * 4 + i;
        int ql = qbase + m;
        int oy = ql >> 8, ox = ql & 255;
        float gy = (2.0f * oy + 1.0f) * (1.0f / 256.0f) - 1.0f;
        float gx = (2.0f * ox + 1.0f) * (1.0f / 256.0f) - 1.0f;
        float gx2 = gx + offs[m * 2 + 0];
        float gy2 = gy + offs[m * 2 + 1];
        int ix0, iy0;
        float wx[4], wy[4];
        prep_axis(gx2, ix0, wx);
        prep_axis(gy2, iy0, wy);
        float v = sample_c(xb, lane, ix0, iy0, wx, wy);
        outst[lane * 33 + m] = v * (1.0f + routs[m * 33 + lane]);
    }
    __syncthreads();

    // ---- writeout -------------------------------------------------------------
    {
        int c = tid >> 3;
        int part = tid & 7;
        const float* src = outst + c * 33 + part * 4;
        float* dst = out + ((size_t)(b * Cn + c)) * QPB + qbase + part * 4;
        *reinterpret_cast<float4*>(dst) =
            make_float4(src[0], src[1], src[2], src[3]);
    }
}

// ===========================================================================
// kernel_launch — 2 launches: setup (xt + prep), fused
// ===========================================================================
extern "C" void kernel_launch(void* const* d_in, const int* in_sizes, int n_in,
                              void* d_out, int out_size) {
    const float* x   = (const float*)d_in[0];
    const float* w0  = (const float*)d_in[1];
    const float* b0  = (const float*)d_in[2];
    const float* w1  = (const float*)d_in[3];
    const float* b1  = (const float*)d_in[4];
    const float* w2  = (const float*)d_in[5];
    const float* b2  = (const float*)d_in[6];
    const float* rw0 = (const float*)d_in[7];
    const float* rb0 = (const float*)d_in[8];
    const float* rw1 = (const float*)d_in[9];
    const float* rb1 = (const float*)d_in[10];
    const float* ow0 = (const float*)d_in[11];
    const float* ob0 = (const float*)d_in[12];
    const float* ow1 = (const float*)d_in[13];
    const float* ob1 = (const float*)d_in[14];
    float* out = (float*)d_out;

    setup_kernel<<<dim3(512, 8), 256>>>(x, w0, w1, w2, rw0, rw1, ow0, ow1);

    cudaFuncSetAttribute(fused_kernel,
                         cudaFuncAttributeMaxDynamicSharedMemorySize, SMEM_BYTES);
    fused_kernel<<<NCTA, 256, SMEM_BYTES>>>(b0, b1, b2, rb0, rb1, ob0, ob1, out);
}

// round 16
// speedup vs baseline: 1.5249x; 1.0204x over previous
#include <cuda_runtime.h>
#include <cuda_fp16.h>
#include <cstdint>

// ===========================================================================
// Problem constants (fixed: B=4, C=32, H=W=128, scale=2)
// ===========================================================================
#define Bn    4
#define Cn    32
#define Hn    128
#define Wn    128
#define QPB   65536
#define NQ    (Bn * QPB)
#define MT    32                   // queries per CTA
#define NCTA  (NQ / MT)            // 8192
#define NRB   2                    // row-blocks (16 rows) per CTA

// ===========================================================================
// Global scratch
// ===========================================================================
__device__ float g_xt[Bn * Hn * Wn * Cn];   // channels-last x

// Weight images: B-fragment-packed fp16.
#define WOFF_L1  0u          // KC=3,  NPT=16 -> 24576
#define WOFF_L2  24576u      // KC=16, NPT=16 -> 131072
#define WOFF_L3  155648u     // KC=16, NPT=2  -> 16384
#define WOFF_R0  172032u     // KC=2,  NPT=16 -> 16384
#define WOFF_R1  188416u     // KC=16, NPT=2  -> 16384
#define WOFF_O0  204800u     // KC=2,  NPT=16 -> 16384
#define WOFF_O1  221184u     // KC=16, NPT=1  -> 8192
#define WIMG_TOTAL 229376u
__device__ __align__(16) unsigned char g_wimg[WIMG_TOTAL];

// ===========================================================================
// Setup kernel: y==0 -> transpose x; y>=1 -> weight prep for layer y-1.
// ===========================================================================
__global__ void setup_kernel(const float* __restrict__ x,
                             const float* __restrict__ w0, const float* __restrict__ w1,
                             const float* __restrict__ w2, const float* __restrict__ rw0,
                             const float* __restrict__ rw1, const float* __restrict__ ow0,
                             const float* __restrict__ ow1) {
    const int tid = threadIdx.x;
    if (blockIdx.y == 0) {
        __shared__ float s[Cn][Wn + 1];
        const int by = blockIdx.x;      // 0..511
#pragma unroll
        for (int it = 0; it < 16; ++it) {
            int idx = tid + it * 256;
            int c = idx >> 7, xc = idx & 127;
            int b = by >> 7, y = by & 127;
            s[c][xc] = x[((b * Cn + c) * Hn + y) * Wn + xc];
        }
        __syncthreads();
#pragma unroll
        for (int it = 0; it < 16; ++it) {
            int idx = tid + it * 256;
            int xc = idx >> 5, c = idx & 31;
            g_xt[(by * Wn + xc) * Cn + c] = s[c][xc];
        }
        return;
    }
    const float* W;
    int Kdim, Ndim, Kt, Nt;
    uint32_t dstOff;
    switch (blockIdx.y - 1) {
        case 0: W = w0;  Kdim = 36;  Ndim = 256; Kt = 48;  Nt = 256; dstOff = WOFF_L1; break;
        case 1: W = w1;  Kdim = 256; Ndim = 256; Kt = 256; Nt = 256; dstOff = WOFF_L2; break;
        case 2: W = w2;  Kdim = 256; Ndim = 32;  Kt = 256; Nt = 32;  dstOff = WOFF_L3; break;
        case 3: W = rw0; Kdim = 32;  Ndim = 256; Kt = 32;  Nt = 256; dstOff = WOFF_R0; break;
        case 4: W = rw1; Kdim = 256; Ndim = 32;  Kt = 256; Nt = 32;  dstOff = WOFF_R1; break;
        case 5: W = ow0; Kdim = 32;  Ndim = 256; Kt = 32;  Nt = 256; dstOff = WOFF_O0; break;
        default: W = ow1; Kdim = 256; Ndim = 2;  Kt = 256; Nt = 16;  dstOff = WOFF_O1; break;
    }
    int idx = blockIdx.x * 256 + tid;
    if (idx >= Kt * Nt) return;
    int k = idx / Nt;
    int n = idx % Nt;
    float w = (k < Kdim && n < Ndim) ? W[k * Ndim + n] : 0.0f;
    __half hb = __float2half_rn(w);
    int kc = k >> 4, ki = k & 15;
    int nc = n >> 3, ni = n & 7;
    int npair = nc >> 1;
    int lane = ni * 4 + ((ki & 7) >> 1);
    int word = (ki >> 3) + (nc & 1) * 2;
    int half = ki & 1;
    uint32_t off = (uint32_t)(((kc * (Nt >> 4) + npair) * 32 + lane) * 16 +
                              word * 4 + half * 2);
    *reinterpret_cast<unsigned short*>(g_wimg + dstOff + off) = __half_as_ushort(hb);
}

// ===========================================================================
// Bicubic helpers (torch aten, A=-0.75)
// ===========================================================================
__device__ __forceinline__ void prep_axis(float g, int& i0, float w[4]) {
    float p = ((g + 1.0f) * 128.0f - 1.0f) * 0.5f;
    float fp = floorf(p);
    i0 = (int)fp;
    float t = p - fp;
    const float A = -0.75f;
    float xx = t + 1.0f;
    w[0] = ((A * xx - 5.0f * A) * xx + 8.0f * A) * xx - 4.0f * A;
    w[1] = ((A + 2.0f) * t - (A + 3.0f)) * t * t + 1.0f;
    float s = 1.0f - t;
    w[2] = ((A + 2.0f) * s - (A + 3.0f)) * s * s + 1.0f;
    w[3] = 1.0f - w[0] - w[1] - w[2];
}

// guarded (boundary) path
__device__ __forceinline__ float sample_slow(const float* __restrict__ xb, int lane,
                                             int ix0, int iy0,
                                             const float* wx, const float* wy) {
    float acc = 0.0f;
#pragma unroll
    for (int i = 0; i < 4; ++i) {
        int yi = iy0 - 1 + i;
        if ((unsigned)yi < 128u) {
            const float* rp = xb + yi * (Wn * Cn) + lane;
            float r = 0.0f;
#pragma unroll
            for (int j = 0; j < 4; ++j) {
                int xj = ix0 - 1 + j;
                if ((unsigned)xj < 128u) r = fmaf(wx[j], __ldg(rp + xj * Cn), r);
            }
            acc = fmaf(wy[i], r, acc);
        }
    }
    return acc;
}

// unguarded interior path (ix0 in [1,125], iy0 in [1,125]); warp-uniform branch
__device__ __forceinline__ float sample_c(const float* __restrict__ xb, int lane,
                                          int ix0, int iy0,
                                          const float* wx, const float* wy) {
    if ((unsigned)(ix0 - 1) <= 124u && (unsigned)(iy0 - 1) <= 124u) {
        const float* rp = xb + (iy0 - 1) * (Wn * Cn) + (ix0 - 1) * Cn + lane;
        float acc = 0.0f;
#pragma unroll
        for (int i = 0; i < 4; ++i) {
            float r = wx[0] * __ldg(rp);
            r = fmaf(wx[1], __ldg(rp + Cn), r);
            r = fmaf(wx[2], __ldg(rp + 2 * Cn), r);
            r = fmaf(wx[3], __ldg(rp + 3 * Cn), r);
            acc = fmaf(wy[i], r, acc);
            rp += Wn * Cn;
        }
        return acc;
    }
    return sample_slow(xb, lane, ix0, iy0, wx, wy);
}

// packed fp16x2 (v1 in high half, v0 in low half)
__device__ __forceinline__ uint32_t pack_h2(float v0, float v1) {
    __half2 h = __floats2half2_rn(v0, v1);
    return *reinterpret_cast<uint32_t*>(&h);
}

// ===========================================================================
// mma.sync m16n8k16 fp16
// ===========================================================================
__device__ __forceinline__ void mma_f16(float* c, const uint4& a,
                                        uint32_t b0, uint32_t b1) {
    asm("mma.sync.aligned.m16n8k16.row.col.f32.f16.f16.f32 "
        "{%0,%1,%2,%3},{%4,%5,%6,%7},{%8,%9},{%0,%1,%2,%3};"
        : "+f"(c[0]), "+f"(c[1]), "+f"(c[2]), "+f"(c[3])
        : "r"(a.x), "r"(a.y), "r"(a.z), "r"(a.w), "r"(b0), "r"(b1));
}

// Wide K-loop over BOTH 16-row blocks, single-term: C += A*B.
template <int KC, int NC, int NPT>
__device__ __forceinline__ void mma_layer(const uint4* __restrict__ aHi,
                                          const uint4* __restrict__ bHi,
                                          int nc0, float C[2][NC][4]) {
    const int lane = threadIdx.x & 31;
#pragma unroll
    for (int r = 0; r < 2; ++r)
#pragma unroll
        for (int j = 0; j < NC; ++j)
#pragma unroll
            for (int t = 0; t < 4; ++t) C[r][j][t] = 0.0f;
    const int npair0 = nc0 >> 1;
#pragma unroll 4
    for (int kc = 0; kc < KC; ++kc) {
        uint4 ah0 = aHi[(kc * NRB + 0) * 32 + lane];
        uint4 ah1 = aHi[(kc * NRB + 1) * 32 + lane];
#pragma unroll
        for (int p = 0; p < NC / 2; ++p) {
            uint4 bh = __ldg(bHi + (kc * NPT + npair0 + p) * 32 + lane);
            mma_f16(C[0][2 * p], ah0, bh.x, bh.y);
            mma_f16(C[1][2 * p], ah1, bh.x, bh.y);
            mma_f16(C[0][2 * p + 1], ah0, bh.z, bh.w);
            mma_f16(C[1][2 * p + 1], ah1, bh.z, bh.w);
        }
    }
}

// Partial K-slice for narrow (N<=32) layers: one npair, kc in [kc0, kc0+kcn).
__device__ __forceinline__ void mma_part(const uint4* __restrict__ aHi,
                                         const uint4* __restrict__ bHi,
                                         int npair0, int kc0, int kcn, int NPT,
                                         float C[2][2][4]) {
    const int lane = threadIdx.x & 31;
#pragma unroll
    for (int r = 0; r < 2; ++r)
#pragma unroll
        for (int j = 0; j < 2; ++j)
#pragma unroll
            for (int t = 0; t < 4; ++t) C[r][j][t] = 0.0f;
#pragma unroll 4
    for (int kc = kc0; kc < kc0 + kcn; ++kc) {
        uint4 ah0 = aHi[(kc * NRB + 0) * 32 + lane];
        uint4 ah1 = aHi[(kc * NRB + 1) * 32 + lane];
        uint4 bh = __ldg(bHi + (kc * NPT + npair0) * 32 + lane);
        mma_f16(C[0][0], ah0, bh.x, bh.y);
        mma_f16(C[1][0], ah1, bh.x, bh.y);
        mma_f16(C[0][1], ah0, bh.z, bh.w);
        mma_f16(C[1][1], ah1, bh.z, bh.w);
    }
}

// Partial K-slice, FIRST n-chunk only (O1: real N=2 lives in chunk 0).
__device__ __forceinline__ void mma_part1(const uint4* __restrict__ aHi,
                                          const uint4* __restrict__ bHi,
                                          int kc0, int kcn, float C[2][4]) {
    const int lane = threadIdx.x & 31;
#pragma unroll
    for (int r = 0; r < 2; ++r)
#pragma unroll
        for (int t = 0; t < 4; ++t) C[r][t] = 0.0f;
#pragma unroll 2
    for (int kc = kc0; kc < kc0 + kcn; ++kc) {
        uint4 ah0 = aHi[(kc * NRB + 0) * 32 + lane];
        uint4 ah1 = aHi[(kc * NRB + 1) * 32 + lane];
        uint4 bh = __ldg(bHi + kc * 32 + lane);   // NPT=1, npair0=0
        mma_f16(C[0], ah0, bh.x, bh.y);
        mma_f16(C[1], ah1, bh.x, bh.y);
    }
}

// Store a warp's narrow-layer partials to scratch (conflict-free float4 layout).
__device__ __forceinline__ void store_part(float4* scr4, int slice,
                                           float C[2][2][4]) {
    const int lane = threadIdx.x & 31;
#pragma unroll
    for (int r = 0; r < 2; ++r)
#pragma unroll
        for (int j = 0; j < 2; ++j) {
            int i = r * 2 + j;
            scr4[(i * 8 + slice) * 32 + lane] =
                make_float4(C[r][j][0], C[r][j][1], C[r][j][2], C[r][j][3]);
        }
}

// Reduce 4 k-slices (slices nh, nh+2, nh+4, nh+6) for n-half nh.
__device__ __forceinline__ void reduce4(const float4* scr4, int nh,
                                        float C[2][2][4]) {
    const int lane = threadIdx.x & 31;
#pragma unroll
    for (int i = 0; i < 4; ++i) {
        float4 a = scr4[(i * 8 + nh) * 32 + lane];
        float4 b = scr4[(i * 8 + 2 + nh) * 32 + lane];
        float4 c = scr4[(i * 8 + 4 + nh) * 32 + lane];
        float4 d = scr4[(i * 8 + 6 + nh) * 32 + lane];
        C[i >> 1][i & 1][0] = (a.x + b.x) + (c.x + d.x);
        C[i >> 1][i & 1][1] = (a.y + b.y) + (c.y + d.y);
        C[i >> 1][i & 1][2] = (a.z + b.z) + (c.z + d.z);
        C[i >> 1][i & 1][3] = (a.w + b.w) + (c.w + d.w);
    }
}

// Epilogue: bias(+ReLU), pack fp16 A fragments for the next layer.
template <int NC, bool RELU>
__device__ __forceinline__ void epi_region(float C[2][NC][4],
                                           const float* __restrict__ biasp,
                                           int nc0, uint32_t* dHi) {
    const int lane = threadIdx.x & 31;
    const int q = (lane & 3) * 2;
#pragma unroll
    for (int j = 0; j < NC; ++j) {
        int nc = nc0 + j;
        int kc = nc >> 1, odd = nc & 1;
        float b0 = __ldg(biasp + nc * 8 + q);
        float b1 = __ldg(biasp + nc * 8 + q + 1);
#pragma unroll
        for (int r = 0; r < 2; ++r) {
            float v0 = C[r][j][0] + b0, v1 = C[r][j][1] + b1;
            float v2 = C[r][j][2] + b0, v3 = C[r][j][3] + b1;
            if (RELU) {
                v0 = fmaxf(v0, 0.f); v1 = fmaxf(v1, 0.f);
                v2 = fmaxf(v2, 0.f); v3 = fmaxf(v3, 0.f);
            }
            int base = ((kc * NRB + r) * 32 + lane) * 4 + odd * 2;
            dHi[base] = pack_h2(v0, v1);
            dHi[base + 1] = pack_h2(v2, v3);
        }
    }
}

// ===========================================================================
// SMEM layout (bytes) — total 32256; 4 CTAs/SM
// ===========================================================================
#define SM_INPF  0          // fp32 [32][49] = 6272 (reused as routs [32][33])
#define SM_SHI   6272       // inp frags: 3*2*512 = 3072
#define SM_PHI   9344       // pred frags: 2*2*512 = 2048
#define SM_AHI   11392      // act frags: 16*2*512 = 16384 (doubles as scratch)
#define SM_OFFS  27776      // fp32 [32][2] = 256
#define SM_OUT   28032      // fp32 [32][33] = 4224
#define SMEM_BYTES 32256

// ===========================================================================
// Fused kernel: 32 queries per CTA, 8 warps, 4 CTAs/SM.
// Wide layers: warp = unique 32 N-cols. Narrow layers: k-split over all warps.
// ===========================================================================
__global__ __launch_bounds__(256, 4) void fused_kernel(
    const float* __restrict__ b0p, const float* __restrict__ b1p,
    const float* __restrict__ b2p, const float* __restrict__ rb0p,
    const float* __restrict__ rb1p, const float* __restrict__ ob0p,
    const float* __restrict__ ob1p, float* __restrict__ out) {
    extern __shared__ __align__(16) unsigned char smraw[];
    float* inpF = reinterpret_cast<float*>(smraw + SM_INPF);
    uint4* SHi = reinterpret_cast<uint4*>(smraw + SM_SHI);
    uint4* PHi = reinterpret_cast<uint4*>(smraw + SM_PHI);
    uint4* AHi = reinterpret_cast<uint4*>(smraw + SM_AHI);
    uint32_t* PHiW = reinterpret_cast<uint32_t*>(PHi);
    uint32_t* AHiW = reinterpret_cast<uint32_t*>(AHi);
    float4* scr4 = reinterpret_cast<float4*>(smraw + SM_AHI);  // narrow-layer scratch
    float* offs  = reinterpret_cast<float*>(smraw + SM_OFFS);
    float* outst = reinterpret_cast<float*>(smraw + SM_OUT);
    float* routs = inpF;   // reuse after L1 staging

    const int tid = threadIdx.x;
    const int lane = tid & 31;
    const int wid = tid >> 5;

    const int q0 = blockIdx.x * MT;
    const int b = q0 >> 16;
    const int qbase = q0 & (QPB - 1);
    const float* xb = g_xt + b * (Hn * Wn * Cn);

    const uint4* WL1 = (const uint4*)(g_wimg + WOFF_L1);
    const uint4* WL2 = (const uint4*)(g_wimg + WOFF_L2);
    const uint4* WL3 = (const uint4*)(g_wimg + WOFF_L3);
    const uint4* WR0 = (const uint4*)(g_wimg + WOFF_R0);
    const uint4* WR1 = (const uint4*)(g_wimg + WOFF_R1);
    const uint4* WO0 = (const uint4*)(g_wimg + WOFF_O0);
    const uint4* WO1 = (const uint4*)(g_wimg + WOFF_O1);

    // ---- Stage A: sampling -> inpF [32][49] --------------------------------
    // All 32 queries of this CTA live in ONE output row: y-work is CTA-uniform.
    // scale=2: a warp's 4 consecutive queries share a 4-row x 6-col tap window.
    {
        const int oy = qbase >> 8;
        float gy = (2.0f * oy + 1.0f) * (1.0f / 256.0f) - 1.0f;
        int iy0;
        float wy[4];
        prep_axis(gy, iy0, wy);
        // uniform y-side rel-coord terms
        float syw = 0.f, sy = 0.f;
#pragma unroll
        for (int ii = 0; ii < 4; ++ii) {
            int yi = iy0 - 1 + ii;
            if ((unsigned)yi < 128u) {
                float yco = (2.0f * yi + 1.0f) * (1.0f / 128.0f) - 1.0f;
                syw += wy[ii]; sy = fmaf(wy[ii], yco, sy);
            }
        }

        const int ox0 = (qbase & 255) + wid * 4;       // divisible by 4
        const int xc0 = (ox0 >> 1) - 2;                // leftmost tap column
        // phase weight vectors: q0/q2 -> t=0.75 (wxA), q1/q3 -> t=0.25 (wxB)
        float gxA = (2.0f * ox0 + 1.0f) * (1.0f / 256.0f) - 1.0f;
        float gxB = (2.0f * (ox0 + 1) + 1.0f) * (1.0f / 256.0f) - 1.0f;
        int ixA, ixB;
        float wxA[4], wxB[4];
        prep_axis(gxA, ixA, wxA);
        prep_axis(gxB, ixB, wxB);

        const bool fast = (xc0 >= 0) && (xc0 + 5 <= 127) &&
                          (iy0 >= 1) && (iy0 <= 125);
        if (fast) {
            const float* rp = xb + (iy0 - 1) * (Wn * Cn) + xc0 * Cn + lane;
            float a0 = 0.f, a1 = 0.f, a2 = 0.f, a3 = 0.f;
#pragma unroll
            for (int i = 0; i < 4; ++i) {
                float v0 = __ldg(rp);
                float v1 = __ldg(rp + Cn);
                float v2 = __ldg(rp + 2 * Cn);
                float v3 = __ldg(rp + 3 * Cn);
                float v4 = __ldg(rp + 4 * Cn);
                float v5 = __ldg(rp + 5 * Cn);
                // same fmaf chain order as sample_c interior path
                float r0 = wxA[0] * v0;
                r0 = fmaf(wxA[1], v1, r0); r0 = fmaf(wxA[2], v2, r0);
                r0 = fmaf(wxA[3], v3, r0);
                float r1 = wxB[0] * v1;
                r1 = fmaf(wxB[1], v2, r1); r1 = fmaf(wxB[2], v3, r1);
                r1 = fmaf(wxB[3], v4, r1);
                float r2 = wxA[0] * v1;
                r2 = fmaf(wxA[1], v2, r2); r2 = fmaf(wxA[2], v3, r2);
                r2 = fmaf(wxA[3], v4, r2);
                float r3 = wxB[0] * v2;
                r3 = fmaf(wxB[1], v3, r3); r3 = fmaf(wxB[2], v4, r3);
                r3 = fmaf(wxB[3], v5, r3);
                a0 = fmaf(wy[i], r0, a0);
                a1 = fmaf(wy[i], r1, a1);
                a2 = fmaf(wy[i], r2, a2);
                a3 = fmaf(wy[i], r3, a3);
                rp += Wn * Cn;
            }
            const int m0 = wid * 4;
            inpF[m0 * 49 + lane] = a0;
            inpF[(m0 + 1) * 49 + lane] = a1;
            inpF[(m0 + 2) * 49 + lane] = a2;
            inpF[(m0 + 3) * 49 + lane] = a3;
        } else {
#pragma unroll
            for (int i = 0; i < 4; ++i) {
                int m = wid * 4 + i;
                float gx = (2.0f * (ox0 + i) + 1.0f) * (1.0f / 256.0f) - 1.0f;
                int ix0;
                float wx[4];
                prep_axis(gx, ix0, wx);
                inpF[m * 49 + lane] = sample_c(xb, lane, ix0, iy0, wx, wy);
            }
        }

        // lane0: rel-coords; lanes 4..15: pad
#pragma unroll
        for (int i = 0; i < 4; ++i) {
            int m = wid * 4 + i;
            if (lane == 0) {
                float gx = (2.0f * (ox0 + i) + 1.0f) * (1.0f / 256.0f) - 1.0f;
                int ix0;
                float wx[4];
                prep_axis(gx, ix0, wx);
                float sxw = 0.f, sx = 0.f;
#pragma unroll
                for (int jj = 0; jj < 4; ++jj) {
                    int xj = ix0 - 1 + jj;
                    if ((unsigned)xj < 128u) {
                        float xco = (2.0f * xj + 1.0f) * (1.0f / 128.0f) - 1.0f;
                        sxw += wx[jj]; sx = fmaf(wx[jj], xco, sx);
                    }
                }
                inpF[m * 49 + 32] = (gy - sy * sxw) * 128.0f;
                inpF[m * 49 + 33] = (gx - sx * syw) * 128.0f;
                int ql = qbase + m;
                float rc = (ql < 2) ? 1.0f : 128.0f;   // faithful cell quirk
                inpF[m * 49 + 34] = rc;
                inpF[m * 49 + 35] = rc;
            }
            if (lane >= 4 && lane < 16) inpF[m * 49 + 32 + lane] = 0.0f;  // pad
        }
    }
    __syncthreads();

    // ---- Stage S frags: inpF -> S (A-fragment fp16, K=48) -------------------
    if (wid < 6) {
        int kc = wid >> 1, rbs = wid & 1;
        int r0 = rbs * 16 + (lane >> 2);
        int k0 = kc * 16 + (lane & 3) * 2;
        uint4 hi;
        hi.x = pack_h2(inpF[r0 * 49 + k0], inpF[r0 * 49 + k0 + 1]);
        hi.y = pack_h2(inpF[(r0 + 8) * 49 + k0], inpF[(r0 + 8) * 49 + k0 + 1]);
        hi.z = pack_h2(inpF[r0 * 49 + k0 + 8], inpF[r0 * 49 + k0 + 9]);
        hi.w = pack_h2(inpF[(r0 + 8) * 49 + k0 + 8], inpF[(r0 + 8) * 49 + k0 + 9]);
        SHi[(kc * NRB + rbs) * 32 + lane] = hi;
    }
    __syncthreads();

    float C4[2][4][4];
    float C2[2][2][4];

    // ---- L1: S(K=48) x W0 -> h1 (N=256) -> A --------------------------------
    mma_layer<3, 4, 16>(SHi, WL1, wid * 4, C4);
    epi_region<4, true>(C4, b0p, wid * 4, AHiW);
    __syncthreads();

    // ---- L2: A(K=256) x W1 -> h2 (N=256) -> A (in place) --------------------
    mma_layer<16, 4, 16>(AHi, WL2, wid * 4, C4);
    __syncthreads();
    epi_region<4, true>(C4, b1p, wid * 4, AHiW);
    __syncthreads();

    // ---- L3 (k-split): A(K=256) x W2 -> pred (N=32) -> P --------------------
    mma_part(AHi, WL3, wid & 1, (wid >> 1) * 4, 4, 2, C2);
    __syncthreads();                     // all reads of A done
    store_part(scr4, wid, C2);
    __syncthreads();
    if (wid < 2) {
        reduce4(scr4, wid, C2);
        epi_region<2, false>(C2, b2p, wid * 2, PHiW);
    }
    __syncthreads();

    // ---- O0: P(K=32) x OW0 -> off-hidden (N=256) -> A ------------------------
    mma_layer<2, 4, 16>(PHi, WO0, wid * 4, C4);
    epi_region<4, true>(C4, ob0p, wid * 4, AHiW);
    __syncthreads();

    // ---- O1 (k-split, chunk 0 only): A(K=256) x OW1 -> offsets; R0 overlaps --
    float C2b[2][4];
    mma_part1(AHi, WO1, wid * 2, 2, C2b);
    __syncthreads();                     // all reads of A done
    {   // store only i = r*2 rows (chunk j=0) — matches reduction below
#pragma unroll
        for (int r = 0; r < 2; ++r)
            scr4[((r * 2) * 8 + wid) * 32 + lane] =
                make_float4(C2b[r][0], C2b[r][1], C2b[r][2], C2b[r][3]);
    }
    __syncthreads();
    if (wid == 0) {
        float o[2][4];
#pragma unroll
        for (int ri = 0; ri < 2; ++ri) {
            int i = ri * 2;
            float4 acc = scr4[(i * 8 + 0) * 32 + lane];
#pragma unroll
            for (int s = 1; s < 8; ++s) {
                float4 v = scr4[(i * 8 + s) * 32 + lane];
                acc.x += v.x; acc.y += v.y; acc.z += v.z; acc.w += v.w;
            }
            o[ri][0] = acc.x; o[ri][1] = acc.y; o[ri][2] = acc.z; o[ri][3] = acc.w;
        }
        if ((lane & 3) == 0) {
            float o0 = __ldg(ob1p + 0), o1 = __ldg(ob1p + 1);
#pragma unroll
            for (int r = 0; r < 2; ++r) {
                int row = r * 16 + (lane >> 2);
                offs[row * 2 + 0] = o[r][0] + o0;
                offs[row * 2 + 1] = o[r][1] + o1;
                offs[(row + 8) * 2 + 0] = o[r][2] + o0;
                offs[(row + 8) * 2 + 1] = o[r][3] + o1;
            }
        }
    }
    // R0 mma overlaps with warp 0's reduction (reads only P-fragments)
    mma_layer<2, 4, 16>(PHi, WR0, wid * 4, C4);
    __syncthreads();                     // offs written; scratch consumed
    epi_region<4, true>(C4, rb0p, wid * 4, AHiW);
    __syncthreads();

    // ---- R1 (k-split): A(K=256) x RW1 -> routing (N=32) -> routs fp32 --------
    mma_part(AHi, WR1, wid & 1, (wid >> 1) * 4, 4, 2, C2);
    __syncthreads();                     // all reads of A done
    store_part(scr4, wid, C2);
    __syncthreads();
    if (wid < 2) {
        reduce4(scr4, wid, C2);
        const int q = (lane & 3) * 2;
#pragma unroll
        for (int j = 0; j < 2; ++j) {
            int nc = wid * 2 + j;
            float bb0 = __ldg(rb1p + nc * 8 + q);
            float bb1 = __ldg(rb1p + nc * 8 + q + 1);
#pragma unroll
            for (int r = 0; r < 2; ++r) {
                int row = r * 16 + (lane >> 2);
                routs[row * 33 + nc * 8 + q]     = C2[r][j][0] + bb0;
                routs[row * 33 + nc * 8 + q + 1] = C2[r][j][1] + bb1;
                routs[(row + 8) * 33 + nc * 8 + q]     = C2[r][j][2] + bb0;
                routs[(row + 8) * 33 + nc * 8 + q + 1] = C2[r][j][3] + bb1;
            }
        }
    }
    __syncthreads();

    // ---- Stage C: offset resample + modulate ---------------------------------
#pragma unroll 2
    for (int i = 0; i < 4; ++i) {
        int m = wid * 4 + i;
        int ql = qbase + m;
        int oy = ql >> 8, ox = ql & 255;
        float gy = (2.0f * oy + 1.0f) * (1.0f / 256.0f) - 1.0f;
        float gx = (2.0f * ox + 1.0f) * (1.0f / 256.0f) - 1.0f;
        float gx2 = gx + offs[m * 2 + 0];
        float gy2 = gy + offs[m * 2 + 1];
        int ix0, iy0;
        float wx[4], wy[4];
        prep_axis(gx2, ix0, wx);
        prep_axis(gy2, iy0, wy);
        float v = sample_c(xb, lane, ix0, iy0, wx, wy);
        outst[lane * 33 + m] = v * (1.0f + routs[m * 33 + lane]);
    }
    __syncthreads();

    // ---- writeout -------------------------------------------------------------
    {
        int c = tid >> 3;
        int part = tid & 7;
        const float* src = outst + c * 33 + part * 4;
        float* dst = out + ((size_t)(b * Cn + c)) * QPB + qbase + part * 4;
        *reinterpret_cast<float4*>(dst) =
            make_float4(src[0], src[1], src[2], src[3]);
    }
}

// ===========================================================================
// kernel_launch — 2 launches: setup (xt + prep), fused
// ===========================================================================
extern "C" void kernel_launch(void* const* d_in, const int* in_sizes, int n_in,
                              void* d_out, int out_size) {
    const float* x   = (const float*)d_in[0];
    const float* w0  = (const float*)d_in[1];
    const float* b0  = (const float*)d_in[2];
    const float* w1  = (const float*)d_in[3];
    const float* b1  = (const float*)d_in[4];
    const float* w2  = (const float*)d_in[5];
    const float* b2  = (const float*)d_in[6];
    const float* rw0 = (const float*)d_in[7];
    const float* rb0 = (const float*)d_in[8];
    const float* rw1 = (const float*)d_in[9];
    const float* rb1 = (const float*)d_in[10];
    const float* ow0 = (const float*)d_in[11];
    const float* ob0 = (const float*)d_in[12];
    const float* ow1 = (const float*)d_in[13];
    const float* ob1 = (const float*)d_in[14];
    float* out = (float*)d_out;

    setup_kernel<<<dim3(512, 8), 256>>>(x, w0, w1, w2, rw0, rw1, ow0, ow1);

    cudaFuncSetAttribute(fused_kernel,
                         cudaFuncAttributeMaxDynamicSharedMemorySize, SMEM_BYTES);
    fused_kernel<<<NCTA, 256, SMEM_BYTES>>>(b0, b1, b2, rb0, rb1, ob0, ob1, out);
}

// round 17
// speedup vs baseline: 1.5277x; 1.0019x over previous
#include <cuda_runtime.h>
#include <cuda_fp16.h>
#include <cstdint>

// ===========================================================================
// Problem constants (fixed: B=4, C=32, H=W=128, scale=2)
// ===========================================================================
#define Bn    4
#define Cn    32
#define Hn    128
#define Wn    128
#define QPB   65536
#define NQ    (Bn * QPB)
#define MT    32                   // queries per CTA
#define NCTA  (NQ / MT)            // 8192
#define NRB   2                    // row-blocks (16 rows) per CTA

// ===========================================================================
// Global scratch
// ===========================================================================
__device__ float g_xt[Bn * Hn * Wn * Cn];   // channels-last x

// Weight images: B-fragment-packed fp16.
#define WOFF_L1  0u          // KC=3,  NPT=16 -> 24576
#define WOFF_L2  24576u      // KC=16, NPT=16 -> 131072
#define WOFF_L3  155648u     // KC=16, NPT=2  -> 16384
#define WOFF_R0  172032u     // KC=2,  NPT=16 -> 16384
#define WOFF_R1  188416u     // KC=16, NPT=2  -> 16384
#define WOFF_O0  204800u     // KC=2,  NPT=16 -> 16384
#define WOFF_O1  221184u     // KC=16, NPT=1  -> 8192
#define WIMG_TOTAL 229376u
__device__ __align__(16) unsigned char g_wimg[WIMG_TOTAL];

// ===========================================================================
// Setup kernel: y==0 -> transpose x; y>=1 -> weight prep for layer y-1.
// ===========================================================================
__global__ void setup_kernel(const float* __restrict__ x,
                             const float* __restrict__ w0, const float* __restrict__ w1,
                             const float* __restrict__ w2, const float* __restrict__ rw0,
                             const float* __restrict__ rw1, const float* __restrict__ ow0,
                             const float* __restrict__ ow1) {
    const int tid = threadIdx.x;
    if (blockIdx.y == 0) {
        __shared__ float s[Cn][Wn + 1];
        const int by = blockIdx.x;      // 0..511
#pragma unroll
        for (int it = 0; it < 16; ++it) {
            int idx = tid + it * 256;
            int c = idx >> 7, xc = idx & 127;
            int b = by >> 7, y = by & 127;
            s[c][xc] = x[((b * Cn + c) * Hn + y) * Wn + xc];
        }
        __syncthreads();
#pragma unroll
        for (int it = 0; it < 16; ++it) {
            int idx = tid + it * 256;
            int xc = idx >> 5, c = idx & 31;
            g_xt[(by * Wn + xc) * Cn + c] = s[c][xc];
        }
        return;
    }
    const float* W;
    int Kdim, Ndim, Kt, Nt;
    uint32_t dstOff;
    switch (blockIdx.y - 1) {
        case 0: W = w0;  Kdim = 36;  Ndim = 256; Kt = 48;  Nt = 256; dstOff = WOFF_L1; break;
        case 1: W = w1;  Kdim = 256; Ndim = 256; Kt = 256; Nt = 256; dstOff = WOFF_L2; break;
        case 2: W = w2;  Kdim = 256; Ndim = 32;  Kt = 256; Nt = 32;  dstOff = WOFF_L3; break;
        case 3: W = rw0; Kdim = 32;  Ndim = 256; Kt = 32;  Nt = 256; dstOff = WOFF_R0; break;
        case 4: W = rw1; Kdim = 256; Ndim = 32;  Kt = 256; Nt = 32;  dstOff = WOFF_R1; break;
        case 5: W = ow0; Kdim = 32;  Ndim = 256; Kt = 32;  Nt = 256; dstOff = WOFF_O0; break;
        default: W = ow1; Kdim = 256; Ndim = 2;  Kt = 256; Nt = 16;  dstOff = WOFF_O1; break;
    }
    int idx = blockIdx.x * 256 + tid;
    if (idx >= Kt * Nt) return;
    int k = idx / Nt;
    int n = idx % Nt;
    float w = (k < Kdim && n < Ndim) ? W[k * Ndim + n] : 0.0f;
    __half hb = __float2half_rn(w);
    int kc = k >> 4, ki = k & 15;
    int nc = n >> 3, ni = n & 7;
    int npair = nc >> 1;
    int lane = ni * 4 + ((ki & 7) >> 1);
    int word = (ki >> 3) + (nc & 1) * 2;
    int half = ki & 1;
    uint32_t off = (uint32_t)(((kc * (Nt >> 4) + npair) * 32 + lane) * 16 +
                              word * 4 + half * 2);
    *reinterpret_cast<unsigned short*>(g_wimg + dstOff + off) = __half_as_ushort(hb);
}

// ===========================================================================
// Bicubic helpers (torch aten, A=-0.75)
// ===========================================================================
__device__ __forceinline__ void prep_axis(float g, int& i0, float w[4]) {
    float p = ((g + 1.0f) * 128.0f - 1.0f) * 0.5f;
    float fp = floorf(p);
    i0 = (int)fp;
    float t = p - fp;
    const float A = -0.75f;
    float xx = t + 1.0f;
    w[0] = ((A * xx - 5.0f * A) * xx + 8.0f * A) * xx - 4.0f * A;
    w[1] = ((A + 2.0f) * t - (A + 3.0f)) * t * t + 1.0f;
    float s = 1.0f - t;
    w[2] = ((A + 2.0f) * s - (A + 3.0f)) * s * s + 1.0f;
    w[3] = 1.0f - w[0] - w[1] - w[2];
}

// guarded (boundary) path
__device__ __forceinline__ float sample_slow(const float* __restrict__ xb, int lane,
                                             int ix0, int iy0,
                                             const float* wx, const float* wy) {
    float acc = 0.0f;
#pragma unroll
    for (int i = 0; i < 4; ++i) {
        int yi = iy0 - 1 + i;
        if ((unsigned)yi < 128u) {
            const float* rp = xb + yi * (Wn * Cn) + lane;
            float r = 0.0f;
#pragma unroll
            for (int j = 0; j < 4; ++j) {
                int xj = ix0 - 1 + j;
                if ((unsigned)xj < 128u) r = fmaf(wx[j], __ldg(rp + xj * Cn), r);
            }
            acc = fmaf(wy[i], r, acc);
        }
    }
    return acc;
}

// unguarded interior path (ix0 in [1,125], iy0 in [1,125]); warp-uniform branch
__device__ __forceinline__ float sample_c(const float* __restrict__ xb, int lane,
                                          int ix0, int iy0,
                                          const float* wx, const float* wy) {
    if ((unsigned)(ix0 - 1) <= 124u && (unsigned)(iy0 - 1) <= 124u) {
        const float* rp = xb + (iy0 - 1) * (Wn * Cn) + (ix0 - 1) * Cn + lane;
        float acc = 0.0f;
#pragma unroll
        for (int i = 0; i < 4; ++i) {
            float r = wx[0] * __ldg(rp);
            r = fmaf(wx[1], __ldg(rp + Cn), r);
            r = fmaf(wx[2], __ldg(rp + 2 * Cn), r);
            r = fmaf(wx[3], __ldg(rp + 3 * Cn), r);
            acc = fmaf(wy[i], r, acc);
            rp += Wn * Cn;
        }
        return acc;
    }
    return sample_slow(xb, lane, ix0, iy0, wx, wy);
}

// packed fp16x2 (v1 in high half, v0 in low half)
__device__ __forceinline__ uint32_t pack_h2(float v0, float v1) {
    __half2 h = __floats2half2_rn(v0, v1);
    return *reinterpret_cast<uint32_t*>(&h);
}

// ===========================================================================
// mma.sync m16n8k16 fp16
// ===========================================================================
__device__ __forceinline__ void mma_f16(float* c, const uint4& a,
                                        uint32_t b0, uint32_t b1) {
    asm("mma.sync.aligned.m16n8k16.row.col.f32.f16.f16.f32 "
        "{%0,%1,%2,%3},{%4,%5,%6,%7},{%8,%9},{%0,%1,%2,%3};"
        : "+f"(c[0]), "+f"(c[1]), "+f"(c[2]), "+f"(c[3])
        : "r"(a.x), "r"(a.y), "r"(a.z), "r"(a.w), "r"(b0), "r"(b1));
}

// Wide K-loop over BOTH 16-row blocks, single-term: C += A*B.
template <int KC, int NC, int NPT>
__device__ __forceinline__ void mma_layer(const uint4* __restrict__ aHi,
                                          const uint4* __restrict__ bHi,
                                          int nc0, float C[2][NC][4]) {
    const int lane = threadIdx.x & 31;
#pragma unroll
    for (int r = 0; r < 2; ++r)
#pragma unroll
        for (int j = 0; j < NC; ++j)
#pragma unroll
            for (int t = 0; t < 4; ++t) C[r][j][t] = 0.0f;
    const int npair0 = nc0 >> 1;
#pragma unroll 4
    for (int kc = 0; kc < KC; ++kc) {
        uint4 ah0 = aHi[(kc * NRB + 0) * 32 + lane];
        uint4 ah1 = aHi[(kc * NRB + 1) * 32 + lane];
#pragma unroll
        for (int p = 0; p < NC / 2; ++p) {
            uint4 bh = __ldg(bHi + (kc * NPT + npair0 + p) * 32 + lane);
            mma_f16(C[0][2 * p], ah0, bh.x, bh.y);
            mma_f16(C[1][2 * p], ah1, bh.x, bh.y);
            mma_f16(C[0][2 * p + 1], ah0, bh.z, bh.w);
            mma_f16(C[1][2 * p + 1], ah1, bh.z, bh.w);
        }
    }
}

// Partial K-slice for narrow (N<=32) layers: one npair, kc in [kc0, kc0+kcn).
__device__ __forceinline__ void mma_part(const uint4* __restrict__ aHi,
                                         const uint4* __restrict__ bHi,
                                         int npair0, int kc0, int kcn, int NPT,
                                         float C[2][2][4]) {
    const int lane = threadIdx.x & 31;
#pragma unroll
    for (int r = 0; r < 2; ++r)
#pragma unroll
        for (int j = 0; j < 2; ++j)
#pragma unroll
            for (int t = 0; t < 4; ++t) C[r][j][t] = 0.0f;
#pragma unroll 4
    for (int kc = kc0; kc < kc0 + kcn; ++kc) {
        uint4 ah0 = aHi[(kc * NRB + 0) * 32 + lane];
        uint4 ah1 = aHi[(kc * NRB + 1) * 32 + lane];
        uint4 bh = __ldg(bHi + (kc * NPT + npair0) * 32 + lane);
        mma_f16(C[0][0], ah0, bh.x, bh.y);
        mma_f16(C[1][0], ah1, bh.x, bh.y);
        mma_f16(C[0][1], ah0, bh.z, bh.w);
        mma_f16(C[1][1], ah1, bh.z, bh.w);
    }
}

// Partial K-slice, FIRST n-chunk only (O1: real N=2 lives in chunk 0).
__device__ __forceinline__ void mma_part1(const uint4* __restrict__ aHi,
                                          const uint4* __restrict__ bHi,
                                          int kc0, int kcn, float C[2][4]) {
    const int lane = threadIdx.x & 31;
#pragma unroll
    for (int r = 0; r < 2; ++r)
#pragma unroll
        for (int t = 0; t < 4; ++t) C[r][t] = 0.0f;
#pragma unroll 2
    for (int kc = kc0; kc < kc0 + kcn; ++kc) {
        uint4 ah0 = aHi[(kc * NRB + 0) * 32 + lane];
        uint4 ah1 = aHi[(kc * NRB + 1) * 32 + lane];
        uint4 bh = __ldg(bHi + kc * 32 + lane);   // NPT=1, npair0=0
        mma_f16(C[0], ah0, bh.x, bh.y);
        mma_f16(C[1], ah1, bh.x, bh.y);
    }
}

// Store a warp's narrow-layer partials to scratch (conflict-free float4 layout).
__device__ __forceinline__ void store_part(float4* scr4, int slice,
                                           float C[2][2][4]) {
    const int lane = threadIdx.x & 31;
#pragma unroll
    for (int r = 0; r < 2; ++r)
#pragma unroll
        for (int j = 0; j < 2; ++j) {
            int i = r * 2 + j;
            scr4[(i * 8 + slice) * 32 + lane] =
                make_float4(C[r][j][0], C[r][j][1], C[r][j][2], C[r][j][3]);
        }
}

// Reduce 4 k-slices (slices nh, nh+2, nh+4, nh+6) for n-half nh.
__device__ __forceinline__ void reduce4(const float4* scr4, int nh,
                                        float C[2][2][4]) {
    const int lane = threadIdx.x & 31;
#pragma unroll
    for (int i = 0; i < 4; ++i) {
        float4 a = scr4[(i * 8 + nh) * 32 + lane];
        float4 b = scr4[(i * 8 + 2 + nh) * 32 + lane];
        float4 c = scr4[(i * 8 + 4 + nh) * 32 + lane];
        float4 d = scr4[(i * 8 + 6 + nh) * 32 + lane];
        C[i >> 1][i & 1][0] = (a.x + b.x) + (c.x + d.x);
        C[i >> 1][i & 1][1] = (a.y + b.y) + (c.y + d.y);
        C[i >> 1][i & 1][2] = (a.z + b.z) + (c.z + d.z);
        C[i >> 1][i & 1][3] = (a.w + b.w) + (c.w + d.w);
    }
}

// Epilogue: bias(+ReLU), pack fp16 A fragments for the next layer.
// Stores as STS.64 (two adjacent words, 8-byte aligned: base is even).
template <int NC, bool RELU>
__device__ __forceinline__ void epi_region(float C[2][NC][4],
                                           const float* __restrict__ biasp,
                                           int nc0, uint32_t* dHi) {
    const int lane = threadIdx.x & 31;
    const int q = (lane & 3) * 2;
#pragma unroll
    for (int j = 0; j < NC; ++j) {
        int nc = nc0 + j;
        int kc = nc >> 1, odd = nc & 1;
        float b0 = __ldg(biasp + nc * 8 + q);
        float b1 = __ldg(biasp + nc * 8 + q + 1);
#pragma unroll
        for (int r = 0; r < 2; ++r) {
            float v0 = C[r][j][0] + b0, v1 = C[r][j][1] + b1;
            float v2 = C[r][j][2] + b0, v3 = C[r][j][3] + b1;
            if (RELU) {
                v0 = fmaxf(v0, 0.f); v1 = fmaxf(v1, 0.f);
                v2 = fmaxf(v2, 0.f); v3 = fmaxf(v3, 0.f);
            }
            int base = ((kc * NRB + r) * 32 + lane) * 4 + odd * 2;
            *reinterpret_cast<uint2*>(dHi + base) =
                make_uint2(pack_h2(v0, v1), pack_h2(v2, v3));
        }
    }
}

// ===========================================================================
// SMEM layout (bytes) — total 32256; 4 CTAs/SM
// ===========================================================================
#define SM_INPF  0          // fp32 [32][49] = 6272 (reused as routs [32][33])
#define SM_SHI   6272       // inp frags: 3*2*512 = 3072
#define SM_PHI   9344       // pred frags: 2*2*512 = 2048
#define SM_AHI   11392      // act frags: 16*2*512 = 16384 (doubles as scratch)
#define SM_OFFS  27776      // fp32 [32][2] = 256
#define SM_OUT   28032      // fp32 [32][33] = 4224
#define SMEM_BYTES 32256

// ===========================================================================
// Fused kernel: 32 queries per CTA, 8 warps, 4 CTAs/SM.
// Wide layers: warp = unique 32 N-cols. Narrow layers: k-split over all warps.
// ===========================================================================
__global__ __launch_bounds__(256, 4) void fused_kernel(
    const float* __restrict__ b0p, const float* __restrict__ b1p,
    const float* __restrict__ b2p, const float* __restrict__ rb0p,
    const float* __restrict__ rb1p, const float* __restrict__ ob0p,
    const float* __restrict__ ob1p, float* __restrict__ out) {
    extern __shared__ __align__(16) unsigned char smraw[];
    float* inpF = reinterpret_cast<float*>(smraw + SM_INPF);
    uint4* SHi = reinterpret_cast<uint4*>(smraw + SM_SHI);
    uint4* PHi = reinterpret_cast<uint4*>(smraw + SM_PHI);
    uint4* AHi = reinterpret_cast<uint4*>(smraw + SM_AHI);
    uint32_t* PHiW = reinterpret_cast<uint32_t*>(PHi);
    uint32_t* AHiW = reinterpret_cast<uint32_t*>(AHi);
    float4* scr4 = reinterpret_cast<float4*>(smraw + SM_AHI);  // narrow-layer scratch
    float* offs  = reinterpret_cast<float*>(smraw + SM_OFFS);
    float* outst = reinterpret_cast<float*>(smraw + SM_OUT);
    float* routs = inpF;   // reuse after L1 staging

    const int tid = threadIdx.x;
    const int lane = tid & 31;
    const int wid = tid >> 5;

    const int q0 = blockIdx.x * MT;
    const int b = q0 >> 16;
    const int qbase = q0 & (QPB - 1);
    const float* xb = g_xt + b * (Hn * Wn * Cn);

    const uint4* WL1 = (const uint4*)(g_wimg + WOFF_L1);
    const uint4* WL2 = (const uint4*)(g_wimg + WOFF_L2);
    const uint4* WL3 = (const uint4*)(g_wimg + WOFF_L3);
    const uint4* WR0 = (const uint4*)(g_wimg + WOFF_R0);
    const uint4* WR1 = (const uint4*)(g_wimg + WOFF_R1);
    const uint4* WO0 = (const uint4*)(g_wimg + WOFF_O0);
    const uint4* WO1 = (const uint4*)(g_wimg + WOFF_O1);

    // ---- Stage A: sampling -> inpF [32][49] --------------------------------
    // All 32 queries of this CTA live in ONE output row: y-work is CTA-uniform.
    // scale=2: a warp's 4 consecutive queries share a 4-row x 6-col tap window.
    {
        const int oy = qbase >> 8;
        float gy = (2.0f * oy + 1.0f) * (1.0f / 256.0f) - 1.0f;
        int iy0;
        float wy[4];
        prep_axis(gy, iy0, wy);
        float syw = 0.f, sy = 0.f;
#pragma unroll
        for (int ii = 0; ii < 4; ++ii) {
            int yi = iy0 - 1 + ii;
            if ((unsigned)yi < 128u) {
                float yco = (2.0f * yi + 1.0f) * (1.0f / 128.0f) - 1.0f;
                syw += wy[ii]; sy = fmaf(wy[ii], yco, sy);
            }
        }

        const int ox0 = (qbase & 255) + wid * 4;       // divisible by 4
        const int xc0 = (ox0 >> 1) - 2;                // leftmost tap column
        float gxA = (2.0f * ox0 + 1.0f) * (1.0f / 256.0f) - 1.0f;
        float gxB = (2.0f * (ox0 + 1) + 1.0f) * (1.0f / 256.0f) - 1.0f;
        int ixA, ixB;
        float wxA[4], wxB[4];
        prep_axis(gxA, ixA, wxA);
        prep_axis(gxB, ixB, wxB);

        const bool fast = (xc0 >= 0) && (xc0 + 5 <= 127) &&
                          (iy0 >= 1) && (iy0 <= 125);
        if (fast) {
            const float* rp = xb + (iy0 - 1) * (Wn * Cn) + xc0 * Cn + lane;
            float a0 = 0.f, a1 = 0.f, a2 = 0.f, a3 = 0.f;
#pragma unroll
            for (int i = 0; i < 4; ++i) {
                float v0 = __ldg(rp);
                float v1 = __ldg(rp + Cn);
                float v2 = __ldg(rp + 2 * Cn);
                float v3 = __ldg(rp + 3 * Cn);
                float v4 = __ldg(rp + 4 * Cn);
                float v5 = __ldg(rp + 5 * Cn);
                float r0 = wxA[0] * v0;
                r0 = fmaf(wxA[1], v1, r0); r0 = fmaf(wxA[2], v2, r0);
                r0 = fmaf(wxA[3], v3, r0);
                float r1 = wxB[0] * v1;
                r1 = fmaf(wxB[1], v2, r1); r1 = fmaf(wxB[2], v3, r1);
                r1 = fmaf(wxB[3], v4, r1);
                float r2 = wxA[0] * v1;
                r2 = fmaf(wxA[1], v2, r2); r2 = fmaf(wxA[2], v3, r2);
                r2 = fmaf(wxA[3], v4, r2);
                float r3 = wxB[0] * v2;
                r3 = fmaf(wxB[1], v3, r3); r3 = fmaf(wxB[2], v4, r3);
                r3 = fmaf(wxB[3], v5, r3);
                a0 = fmaf(wy[i], r0, a0);
                a1 = fmaf(wy[i], r1, a1);
                a2 = fmaf(wy[i], r2, a2);
                a3 = fmaf(wy[i], r3, a3);
                rp += Wn * Cn;
            }
            const int m0 = wid * 4;
            inpF[m0 * 49 + lane] = a0;
            inpF[(m0 + 1) * 49 + lane] = a1;
            inpF[(m0 + 2) * 49 + lane] = a2;
            inpF[(m0 + 3) * 49 + lane] = a3;
        } else {
#pragma unroll
            for (int i = 0; i < 4; ++i) {
                int m = wid * 4 + i;
                float gx = (2.0f * (ox0 + i) + 1.0f) * (1.0f / 256.0f) - 1.0f;
                int ix0;
                float wx[4];
                prep_axis(gx, ix0, wx);
                inpF[m * 49 + lane] = sample_c(xb, lane, ix0, iy0, wx, wy);
            }
        }

        // lane0: rel-coords; lanes 4..15: pad
#pragma unroll
        for (int i = 0; i < 4; ++i) {
            int m = wid * 4 + i;
            if (lane == 0) {
                float gx = (2.0f * (ox0 + i) + 1.0f) * (1.0f / 256.0f) - 1.0f;
                int ix0;
                float wx[4];
                prep_axis(gx, ix0, wx);
                float sxw = 0.f, sx = 0.f;
#pragma unroll
                for (int jj = 0; jj < 4; ++jj) {
                    int xj = ix0 - 1 + jj;
                    if ((unsigned)xj < 128u) {
                        float xco = (2.0f * xj + 1.0f) * (1.0f / 128.0f) - 1.0f;
                        sxw += wx[jj]; sx = fmaf(wx[jj], xco, sx);
                    }
                }
                inpF[m * 49 + 32] = (gy - sy * sxw) * 128.0f;
                inpF[m * 49 + 33] = (gx - sx * syw) * 128.0f;
                int ql = qbase + m;
                float rc = (ql < 2) ? 1.0f : 128.0f;   // faithful cell quirk
                inpF[m * 49 + 34] = rc;
                inpF[m * 49 + 35] = rc;
            }
            if (lane >= 4 && lane < 16) inpF[m * 49 + 32 + lane] = 0.0f;  // pad
        }
    }
    __syncthreads();

    // ---- Stage S frags: inpF -> S (A-fragment fp16, K=48) -------------------
    if (wid < 6) {
        int kc = wid >> 1, rbs = wid & 1;
        int r0 = rbs * 16 + (lane >> 2);
        int k0 = kc * 16 + (lane & 3) * 2;
        uint4 hi;
        hi.x = pack_h2(inpF[r0 * 49 + k0], inpF[r0 * 49 + k0 + 1]);
        hi.y = pack_h2(inpF[(r0 + 8) * 49 + k0], inpF[(r0 + 8) * 49 + k0 + 1]);
        hi.z = pack_h2(inpF[r0 * 49 + k0 + 8], inpF[r0 * 49 + k0 + 9]);
        hi.w = pack_h2(inpF[(r0 + 8) * 49 + k0 + 8], inpF[(r0 + 8) * 49 + k0 + 9]);
        SHi[(kc * NRB + rbs) * 32 + lane] = hi;
    }
    __syncthreads();

    float C4[2][4][4];
    float C2[2][2][4];

    // ---- L1: S(K=48) x W0 -> h1 (N=256) -> A --------------------------------
    mma_layer<3, 4, 16>(SHi, WL1, wid * 4, C4);
    epi_region<4, true>(C4, b0p, wid * 4, AHiW);
    __syncthreads();

    // ---- L2: A(K=256) x W1 -> h2 (N=256) -> A (in place) --------------------
    mma_layer<16, 4, 16>(AHi, WL2, wid * 4, C4);
    __syncthreads();
    epi_region<4, true>(C4, b1p, wid * 4, AHiW);
    __syncthreads();

    // ---- L3 (k-split): A(K=256) x W2 -> pred (N=32) -> P --------------------
    mma_part(AHi, WL3, wid & 1, (wid >> 1) * 4, 4, 2, C2);
    __syncthreads();                     // all reads of A done
    store_part(scr4, wid, C2);
    __syncthreads();
    if (wid < 2) {
        reduce4(scr4, wid, C2);
        epi_region<2, false>(C2, b2p, wid * 2, PHiW);
    }
    __syncthreads();

    // ---- O0: P(K=32) x OW0 -> off-hidden (N=256) -> A ------------------------
    mma_layer<2, 4, 16>(PHi, WO0, wid * 4, C4);
    epi_region<4, true>(C4, ob0p, wid * 4, AHiW);
    __syncthreads();

    // ---- O1 (k-split, chunk 0 only): A(K=256) x OW1 -> offsets; R0 overlaps --
    float C2b[2][4];
    mma_part1(AHi, WO1, wid * 2, 2, C2b);
    __syncthreads();                     // all reads of A done
    {
#pragma unroll
        for (int r = 0; r < 2; ++r)
            scr4[((r * 2) * 8 + wid) * 32 + lane] =
                make_float4(C2b[r][0], C2b[r][1], C2b[r][2], C2b[r][3]);
    }
    __syncthreads();
    if (wid == 0) {
        float o[2][4];
#pragma unroll
        for (int ri = 0; ri < 2; ++ri) {
            int i = ri * 2;
            float4 acc = scr4[(i * 8 + 0) * 32 + lane];
#pragma unroll
            for (int s = 1; s < 8; ++s) {
                float4 v = scr4[(i * 8 + s) * 32 + lane];
                acc.x += v.x; acc.y += v.y; acc.z += v.z; acc.w += v.w;
            }
            o[ri][0] = acc.x; o[ri][1] = acc.y; o[ri][2] = acc.z; o[ri][3] = acc.w;
        }
        if ((lane & 3) == 0) {
            float o0 = __ldg(ob1p + 0), o1 = __ldg(ob1p + 1);
#pragma unroll
            for (int r = 0; r < 2; ++r) {
                int row = r * 16 + (lane >> 2);
                offs[row * 2 + 0] = o[r][0] + o0;
                offs[row * 2 + 1] = o[r][1] + o1;
                offs[(row + 8) * 2 + 0] = o[r][2] + o0;
                offs[(row + 8) * 2 + 1] = o[r][3] + o1;
            }
        }
    }
    // R0 mma overlaps with warp 0's reduction (reads only P-fragments)
    mma_layer<2, 4, 16>(PHi, WR0, wid * 4, C4);
    __syncthreads();                     // offs written; scratch consumed
    epi_region<4, true>(C4, rb0p, wid * 4, AHiW);
    __syncthreads();

    // ---- R1 (k-split): A(K=256) x RW1 -> routing (N=32) -> routs fp32 --------
    mma_part(AHi, WR1, wid & 1, (wid >> 1) * 4, 4, 2, C2);
    __syncthreads();                     // all reads of A done
    store_part(scr4, wid, C2);
    __syncthreads();
    if (wid < 2) {
        reduce4(scr4, wid, C2);
        const int q = (lane & 3) * 2;
#pragma unroll
        for (int j = 0; j < 2; ++j) {
            int nc = wid * 2 + j;
            float bb0 = __ldg(rb1p + nc * 8 + q);
            float bb1 = __ldg(rb1p + nc * 8 + q + 1);
#pragma unroll
            for (int r = 0; r < 2; ++r) {
                int row = r * 16 + (lane >> 2);
                routs[row * 33 + nc * 8 + q]     = C2[r][j][0] + bb0;
                routs[row * 33 + nc * 8 + q + 1] = C2[r][j][1] + bb1;
                routs[(row + 8) * 33 + nc * 8 + q]     = C2[r][j][2] + bb0;
                routs[(row + 8) * 33 + nc * 8 + q + 1] = C2[r][j][3] + bb1;
            }
        }
    }
    __syncthreads();

    // ---- Stage C: offset resample + modulate ---------------------------------
#pragma unroll 2
    for (int i = 0; i < 4; ++i) {
        int m = wid * 4 + i;
        int ql = qbase + m;
        int oy = ql >> 8, ox = ql & 255;
        float gy = (2.0f * oy + 1.0f) * (1.0f / 256.0f) - 1.0f;
        float gx = (2.0f * ox + 1.0f) * (1.0f / 256.0f) - 1.0f;
        float gx2 = gx + offs[m * 2 + 0];
        float gy2 = gy + offs[m * 2 + 1];
        int ix0, iy0;
        float wx[4], wy[4];
        prep_axis(gx2, ix0, wx);
        prep_axis(gy2, iy0, wy);
        float v = sample_c(xb, lane, ix0, iy0, wx, wy);
        outst[lane * 33 + m] = v * (1.0f + routs[m * 33 + lane]);
    }
    __syncthreads();

    // ---- writeout -------------------------------------------------------------
    {
        int c = tid >> 3;
        int part = tid & 7;
        const float* src = outst + c * 33 + part * 4;
        float* dst = out + ((size_t)(b * Cn + c)) * QPB + qbase + part * 4;
        *reinterpret_cast<float4*>(dst) =
            make_float4(src[0], src[1], src[2], src[3]);
    }
}

// ===========================================================================
// kernel_launch — 2 launches: setup (xt + prep), fused
// ===========================================================================
extern "C" void kernel_launch(void* const* d_in, const int* in_sizes, int n_in,
                              void* d_out, int out_size) {
    const float* x   = (const float*)d_in[0];
    const float* w0  = (const float*)d_in[1];
    const float* b0  = (const float*)d_in[2];
    const float* w1  = (const float*)d_in[3];
    const float* b1  = (const float*)d_in[4];
    const float* w2  = (const float*)d_in[5];
    const float* b2  = (const float*)d_in[6];
    const float* rw0 = (const float*)d_in[7];
    const float* rb0 = (const float*)d_in[8];
    const float* rw1 = (const float*)d_in[9];
    const float* rb1 = (const float*)d_in[10];
    const float* ow0 = (const float*)d_in[11];
    const float* ob0 = (const float*)d_in[12];
    const float* ow1 = (const float*)d_in[13];
    const float* ob1 = (const float*)d_in[14];
    float* out = (float*)d_out;

    setup_kernel<<<dim3(512, 8), 256>>>(x, w0, w1, w2, rw0, rw1, ow0, ow1);

    cudaFuncSetAttribute(fused_kernel,
                         cudaFuncAttributeMaxDynamicSharedMemorySize, SMEM_BYTES);
    fused_kernel<<<NCTA, 256, SMEM_BYTES>>>(b0, b1, b2, rb0, rb1, ob0, ob1, out);
}